// round 12
// baseline (speedup 1.0000x reference)
#include <cuda_runtime.h>
#include <cuda_bf16.h>
#include <cstdint>
#include <math.h>

// ---------------------------------------------------------------------------
// Problem constants
// ---------------------------------------------------------------------------
#define BSZ   8192
#define DIN   2048
#define H0D   1024
#define H1D   512
#define LATD  128
#define NC    8

typedef __nv_bfloat16 bf16;

// ---------------------------------------------------------------------------
// Scratch (device globals)
// Weights are stored TILED: per (n-block of 128, k-chunk of 32) a 16 KB pair:
//   [0,8K)  hi tile: row r (=n%128), byte r*64 + ((v ^ ((r>>1)&3))*16) + (k%8)*2
//   [8K,16K) lo tile, same layout.   v = (k%32)/8.
// Tile-pair index = nb*(K/32) + kc;  group stride = (N/128)*(K/32) pairs.
// This is byte-identical to the kernel's smem stage layout -> one bulk copy.
// ---------------------------------------------------------------------------
__device__ bf16 g_xh [(size_t)BSZ * DIN];
__device__ bf16 g_xl [(size_t)BSZ * DIN];
__device__ bf16 g_w0t [(size_t)2 * NC * H0D * DIN];
__device__ bf16 g_w1t [(size_t)2 * H1D * H0D];
__device__ bf16 g_wmut[(size_t)2 * LATD * H1D];
__device__ bf16 g_wlvt[(size_t)2 * LATD * H1D];
__device__ bf16 g_wd0t[(size_t)2 * H1D * LATD];
__device__ bf16 g_wd1t[(size_t)2 * NC * H0D * H1D];
__device__ bf16 g_wot [(size_t)2 * DIN * H0D];
__device__ bf16 g_h0h[(size_t)BSZ * H0D];
__device__ bf16 g_h0l[(size_t)BSZ * H0D];
__device__ bf16 g_d0h[(size_t)BSZ * H1D];
__device__ bf16 g_d0l[(size_t)BSZ * H1D];
__device__ bf16 g_zh [(size_t)BSZ * LATD];
__device__ bf16 g_zl [(size_t)BSZ * LATD];
__device__ int   g_perm[NC * BSZ];
__device__ int   g_counts[NC];

// ---------------------------------------------------------------------------
// Routing
// ---------------------------------------------------------------------------
__global__ void reset_counts_k() {
    if (threadIdx.x < NC) g_counts[threadIdx.x] = 0;
}
__global__ void scatter_k(const int* __restrict__ labels) {
    int b = blockIdx.x * blockDim.x + threadIdx.x;
    if (b < BSZ) {
        int c = labels[b];
        int p = atomicAdd(&g_counts[c], 1);
        g_perm[c * BSZ + p] = b;
    }
}

// ---------------------------------------------------------------------------
// fp32 -> bf16 hi/lo split
// ---------------------------------------------------------------------------
__device__ __forceinline__ void split_bf16(float v, bf16& h, bf16& l) {
    h = __float2bfloat16_rn(v);
    l = __float2bfloat16_rn(v - __bfloat162float(h));
}

__global__ void convert_act_k(const float* __restrict__ X,
                              bf16* __restrict__ H, bf16* __restrict__ L, int n4) {
    int i = blockIdx.x * blockDim.x + threadIdx.x;
    if (i >= n4) return;
    float4 v = reinterpret_cast<const float4*>(X)[i];
    bf16 h0, h1, h2, h3, l0, l1, l2, l3;
    split_bf16(v.x, h0, l0); split_bf16(v.y, h1, l1);
    split_bf16(v.z, h2, l2); split_bf16(v.w, h3, l3);
    __nv_bfloat162 ph0 = __halves2bfloat162(h0, h1);
    __nv_bfloat162 ph1 = __halves2bfloat162(h2, h3);
    __nv_bfloat162 pl0 = __halves2bfloat162(l0, l1);
    __nv_bfloat162 pl1 = __halves2bfloat162(l2, l3);
    uint2 uh = make_uint2(*(uint32_t*)&ph0, *(uint32_t*)&ph1);
    uint2 ul = make_uint2(*(uint32_t*)&pl0, *(uint32_t*)&pl1);
    *reinterpret_cast<uint2*>(H + (size_t)i * 4) = uh;
    *reinterpret_cast<uint2*>(L + (size_t)i * 4) = ul;
}

// Weight convert + transpose into TILED layout. W [K,N] fp32, grid.z = group.
__global__ void convert_wt_k(const float* __restrict__ W,
                             bf16* __restrict__ Tt, int K, int N) {
    __shared__ float tile[32][33];
    int g = blockIdx.z;
    const float* Wg = W + (size_t)g * K * N;
    char* base = reinterpret_cast<char*>(Tt) +
                 (size_t)g * (N >> 7) * (K >> 5) * 16384;
    int n0 = blockIdx.x * 32, k0 = blockIdx.y * 32;
    int tx = threadIdx.x, ty = threadIdx.y;   // 32 x 8
    #pragma unroll
    for (int i = 0; i < 4; i++)
        tile[ty + 8 * i][tx] = Wg[(size_t)(k0 + ty + 8 * i) * N + n0 + tx];
    __syncthreads();
    #pragma unroll
    for (int i = 0; i < 4; i++) {
        int n = n0 + ty + 8 * i;
        int k = k0 + tx;
        float v = tile[tx][ty + 8 * i];
        bf16 h, l;
        split_bf16(v, h, l);
        int nb = n >> 7, kc = k >> 5, r = n & 127;
        int vv = ((k >> 3) & 3) ^ ((r >> 1) & 3);
        size_t off = ((size_t)nb * (K >> 5) + kc) * 16384
                   + (size_t)r * 64 + vv * 16 + (k & 7) * 2;
        *reinterpret_cast<bf16*>(base + off) = h;
        *reinterpret_cast<bf16*>(base + off + 8192) = l;
    }
}

// ---------------------------------------------------------------------------
// PTX wrappers
// ---------------------------------------------------------------------------
__device__ __forceinline__ uint32_t smem_u32(const void* p) {
    uint32_t a;
    asm("{ .reg .u64 t; cvta.to.shared.u64 t, %1; cvt.u32.u64 %0, t; }"
        : "=r"(a) : "l"(p));
    return a;
}

__device__ __forceinline__ void cp_async16(uint32_t saddr, const void* g, bool ok) {
    int sz = ok ? 16 : 0;
    asm volatile("cp.async.cg.shared.global [%0], [%1], 16, %2;"
                 :: "r"(saddr), "l"(g), "r"(sz));
}
#define CP_COMMIT() asm volatile("cp.async.commit_group;" ::: "memory")
#define CP_WAIT(n)  asm volatile("cp.async.wait_group %0;" :: "n"(n) : "memory")

__device__ __forceinline__ void bulk_g2s(uint32_t dst, const void* src,
                                         uint32_t bytes, uint32_t mbar) {
    asm volatile(
        "cp.async.bulk.shared::cluster.global.mbarrier::complete_tx::bytes "
        "[%0], [%1], %2, [%3];"
        :: "r"(dst), "l"(src), "r"(bytes), "r"(mbar) : "memory");
}

#define MBARRIER_INIT(addr, cnt) \
    asm volatile("mbarrier.init.shared.b64 [%0], %1;" \
        :: "r"((uint32_t)(addr)), "r"((uint32_t)(cnt)) : "memory")

#define MBARRIER_EXPECT_TX(addr, tx) \
    asm volatile("mbarrier.arrive.expect_tx.shared.b64 _, [%0], %1;" \
        :: "r"((uint32_t)(addr)), "r"((uint32_t)(tx)) : "memory")

#define MBARRIER_WAIT_PARITY(mbar_smem_addr, phase_parity) do { \
    uint32_t _mbar = (uint32_t)(mbar_smem_addr); \
    uint32_t _parity = (uint32_t)(phase_parity); \
    uint32_t _done; \
    asm volatile( \
        "{\n\t" \
        ".reg .pred p;\n\t" \
        "mbarrier.try_wait.parity.acquire.cta.shared::cta.b64 p, [%1], %2;\n\t" \
        "selp.b32 %0, 1, 0, p;\n\t" \
        "}" \
        : "=r"(_done) : "r"(_mbar), "r"(_parity) : "memory"); \
    if (!_done) { \
        asm volatile( \
            "{\n\t" \
            ".reg .pred P1;\n\t" \
            "WAIT_LOOP_%=:\n\t" \
            "mbarrier.try_wait.parity.acquire.cta.shared::cta.b64 P1, [%0], %1, 0x989680;\n\t" \
            "@P1 bra.uni WAIT_DONE_%=;\n\t" \
            "bra.uni WAIT_LOOP_%=;\n\t" \
            "WAIT_DONE_%=:\n\t" \
            "}" \
            :: "r"(_mbar), "r"(_parity) : "memory"); \
    } \
} while(0)

__device__ __forceinline__ void ldsm_x4(uint32_t* r, uint32_t addr) {
    asm volatile("ldmatrix.sync.aligned.m8n8.x4.shared.b16 {%0,%1,%2,%3}, [%4];"
                 : "=r"(r[0]), "=r"(r[1]), "=r"(r[2]), "=r"(r[3]) : "r"(addr));
}

__device__ __forceinline__ void mma16816(float* c, const uint32_t* a, const uint32_t* b) {
    asm volatile(
        "mma.sync.aligned.m16n8k16.row.col.f32.bf16.bf16.f32 "
        "{%0,%1,%2,%3}, {%4,%5,%6,%7}, {%8,%9}, {%0,%1,%2,%3};"
        : "+f"(c[0]), "+f"(c[1]), "+f"(c[2]), "+f"(c[3])
        : "r"(a[0]), "r"(a[1]), "r"(a[2]), "r"(a[3]), "r"(b[0]), "r"(b[1]));
}

// ---------------------------------------------------------------------------
// mma.sync GEMM: 256x128x32 CTA tile, bf16x3 split, 3-stage pipeline.
// A (activations): cp.async row loads (supports grouped gather).
// B (weights): ONE cp.async.bulk of a pre-tiled 16KB hi+lo pair per stage,
// completing on a per-stage mbarrier. smem swizzle c' = v ^ ((row>>1)&3).
// ---------------------------------------------------------------------------
#define TC_BM 256
#define TC_BN 128
#define TC_KC 32
#define TC_THREADS 512
#define TC_NSTAGE 3

#define A_TILE_B (TC_BM * 64)                    // 16384
#define B_TILE_B (TC_BN * 64)                    // 8192
#define STAGE_B  (2 * A_TILE_B + 2 * B_TILE_B)   // 49152
#define OFF_AH 0
#define OFF_AL A_TILE_B
#define OFF_BH (2 * A_TILE_B)
#define OFF_BL (2 * A_TILE_B + B_TILE_B)
#define SM_ROWS_OFF (TC_NSTAGE * STAGE_B)
#define SM_MBAR_OFF (SM_ROWS_OFF + TC_BM * 4)
#define TC_SMEM_TOTAL (SM_MBAR_OFF + TC_NSTAGE * 8)

__device__ __forceinline__ uint32_t swz_off(int row, int v) {
    return (uint32_t)(row * 64 + ((v ^ ((row >> 1) & 3)) << 4));
}

// A-only stage load (2048 x 16B cp.async ops across 512 threads)
template <bool GROUPED>
__device__ __forceinline__ void tc_load_A(
    uint32_t stage_base, const int* __restrict__ rows, int tid, int k0,
    const bf16* __restrict__ Ah, const bf16* __restrict__ Al,
    int m0, int K)
{
    #pragma unroll
    for (int t = 0; t < 4; t++) {
        int idx = tid + t * TC_THREADS;     // 0..2047
        int tile = idx >> 10;
        int rem  = idx & 1023;
        int row  = rem >> 2;
        int v    = rem & 3;
        int gr = GROUPED ? rows[row] : (m0 + row);
        bool ok = !GROUPED || (gr >= 0);
        const bf16* src = tile ? Al : Ah;
        cp_async16(stage_base + (tile ? OFF_AL : OFF_AH) + swz_off(row, v),
                   src + ((size_t)(ok ? gr : 0) * K + k0 + v * 8), ok);
    }
}

// OUTMODE: 0 = fp32 Out, 1 = bf16 hi/lo Oh/Ol
template <bool RELU, bool GROUPED, int OUTMODE>
__global__ void __launch_bounds__(TC_THREADS, 1)
tc_gemm_k(const bf16* __restrict__ Ah, const bf16* __restrict__ Al,
          const bf16* __restrict__ Bt,
          const float* __restrict__ biasg,
          float* __restrict__ OutF,
          bf16* __restrict__ Oh, bf16* __restrict__ Ol,
          int M, int N, int K)
{
    extern __shared__ char smem[];
    const int tid  = threadIdx.x;
    const int wid  = tid >> 5;
    const int lane = tid & 31;
    const int wm   = wid >> 2;
    const int wn   = wid & 3;
    const int g    = GROUPED ? blockIdx.z : 0;
    const int m0   = blockIdx.y * TC_BM;
    if (GROUPED) {
        if (m0 >= g_counts[g]) return;
    }
    const int n0 = blockIdx.x * TC_BN;
    uint32_t sb = smem_u32(smem);
    int* rows_s = reinterpret_cast<int*>(smem + SM_ROWS_OFF);

    if (GROUPED && tid < TC_BM) {
        int cnt = g_counts[g];
        int r = m0 + tid;
        rows_s[tid] = (r < cnt) ? g_perm[g * BSZ + r] : -1;
    }
    if (tid == 0) {
        #pragma unroll
        for (int s = 0; s < TC_NSTAGE; s++)
            MBARRIER_INIT(sb + SM_MBAR_OFF + s * 8, 1);
    }
    __syncthreads();

    const int nkc = K >> 5;   // tile-pair count along K
    const char* Btb = reinterpret_cast<const char*>(Bt)
        + ((size_t)(GROUPED ? g : 0) * (N >> 7) * nkc
           + (size_t)blockIdx.x * nkc) * 16384;

    float acc[4][4][4];
    #pragma unroll
    for (int i = 0; i < 4; i++)
        #pragma unroll
        for (int j = 0; j < 4; j++)
            #pragma unroll
            for (int q = 0; q < 4; q++) acc[i][j][q] = 0.f;

    const int nchunks = K / TC_KC;

    // prologue: stages 0, 1
    tc_load_A<GROUPED>(sb + 0 * STAGE_B, rows_s, tid, 0, Ah, Al, m0, K);
    CP_COMMIT();
    tc_load_A<GROUPED>(sb + 1 * STAGE_B, rows_s, tid, TC_KC, Ah, Al, m0, K);
    CP_COMMIT();
    if (tid == 0) {
        MBARRIER_EXPECT_TX(sb + SM_MBAR_OFF + 0, 16384);
        bulk_g2s(sb + 0 * STAGE_B + OFF_BH, Btb + (size_t)0 * 16384, 16384,
                 sb + SM_MBAR_OFF + 0);
        if (nchunks > 1) {
            MBARRIER_EXPECT_TX(sb + SM_MBAR_OFF + 8, 16384);
            bulk_g2s(sb + 1 * STAGE_B + OFF_BH, Btb + (size_t)1 * 16384, 16384,
                     sb + SM_MBAR_OFF + 8);
        }
    }

    int stage = 0;
    for (int i = 0; i < nchunks; i++) {
        if (i + 1 < nchunks) { CP_WAIT(1); } else { CP_WAIT(0); }
        MBARRIER_WAIT_PARITY(sb + SM_MBAR_OFF + stage * 8, (i / TC_NSTAGE) & 1);
        __syncthreads();   // stage i ready; all warps done with stage i-1

        if (i + 2 < nchunks) {
            int ps = stage + 2; if (ps >= TC_NSTAGE) ps -= TC_NSTAGE;
            tc_load_A<GROUPED>(sb + ps * STAGE_B, rows_s, tid, (i + 2) * TC_KC,
                               Ah, Al, m0, K);
            CP_COMMIT();
            if (tid == 0) {
                MBARRIER_EXPECT_TX(sb + SM_MBAR_OFF + ps * 8, 16384);
                bulk_g2s(sb + ps * STAGE_B + OFF_BH,
                         Btb + (size_t)(i + 2) * 16384, 16384,
                         sb + SM_MBAR_OFF + ps * 8);
            }
        }

        uint32_t st = sb + stage * STAGE_B;
        #pragma unroll
        for (int kk = 0; kk < 2; kk++) {
            const int vb = kk * 2 + (lane >> 4);
            uint32_t bh[8], bl[8];
            #pragma unroll
            for (int p = 0; p < 2; p++) {
                int brow = wn * 32 + p * 16 + (lane & 15);
                uint32_t r[4];
                ldsm_x4(r, st + OFF_BH + swz_off(brow, vb));
                bh[4 * p + 0] = r[0]; bh[4 * p + 1] = r[2];
                bh[4 * p + 2] = r[1]; bh[4 * p + 3] = r[3];
                ldsm_x4(r, st + OFF_BL + swz_off(brow, vb));
                bl[4 * p + 0] = r[0]; bl[4 * p + 1] = r[2];
                bl[4 * p + 2] = r[1]; bl[4 * p + 3] = r[3];
            }
            uint32_t a[4][4];
            #pragma unroll
            for (int mt = 0; mt < 4; mt++) {
                int arow = wm * 64 + mt * 16 + (lane & 15);
                ldsm_x4(a[mt], st + OFF_AH + swz_off(arow, vb));
            }
            #pragma unroll
            for (int mt = 0; mt < 4; mt++)
                #pragma unroll
                for (int nt = 0; nt < 4; nt++)
                    mma16816(acc[mt][nt], a[mt], &bh[2 * nt]);
            #pragma unroll
            for (int mt = 0; mt < 4; mt++)
                #pragma unroll
                for (int nt = 0; nt < 4; nt++)
                    mma16816(acc[mt][nt], a[mt], &bl[2 * nt]);
            #pragma unroll
            for (int mt = 0; mt < 4; mt++) {
                int arow = wm * 64 + mt * 16 + (lane & 15);
                ldsm_x4(a[mt], st + OFF_AL + swz_off(arow, vb));
            }
            #pragma unroll
            for (int mt = 0; mt < 4; mt++)
                #pragma unroll
                for (int nt = 0; nt < 4; nt++)
                    mma16816(acc[mt][nt], a[mt], &bh[2 * nt]);
        }
        stage = stage + 1; if (stage >= TC_NSTAGE) stage = 0;
    }

    // Epilogue
    const float* bias = biasg + (GROUPED ? (size_t)g * N : 0);
    #pragma unroll
    for (int mt = 0; mt < 4; mt++) {
        #pragma unroll
        for (int half = 0; half < 2; half++) {
            int rloc = wm * 64 + mt * 16 + (lane >> 2) + half * 8;
            int gm = GROUPED ? rows_s[rloc] : (m0 + rloc);
            if (GROUPED && gm < 0) continue;
            #pragma unroll
            for (int nt = 0; nt < 4; nt++) {
                int col = n0 + wn * 32 + nt * 8 + 2 * (lane & 3);
                float c0 = acc[mt][nt][2 * half + 0] + bias[col];
                float c1 = acc[mt][nt][2 * half + 1] + bias[col + 1];
                if (RELU) { c0 = fmaxf(c0, 0.f); c1 = fmaxf(c1, 0.f); }
                if (OUTMODE == 0) {
                    *reinterpret_cast<float2*>(OutF + (size_t)gm * N + col) =
                        make_float2(c0, c1);
                } else {
                    bf16 h0, h1, l0, l1;
                    split_bf16(c0, h0, l0);
                    split_bf16(c1, h1, l1);
                    __nv_bfloat162 ph = __halves2bfloat162(h0, h1);
                    __nv_bfloat162 pl = __halves2bfloat162(l0, l1);
                    *reinterpret_cast<uint32_t*>(Oh + (size_t)gm * N + col) =
                        *reinterpret_cast<uint32_t*>(&ph);
                    *reinterpret_cast<uint32_t*>(Ol + (size_t)gm * N + col) =
                        *reinterpret_cast<uint32_t*>(&pl);
                }
            }
        }
    }
}

// ---------------------------------------------------------------------------
// Reparameterize + hi/lo split: z = mu + eps * exp(0.5 * logvar)
// ---------------------------------------------------------------------------
__global__ void z_k(const float* __restrict__ mu, const float* __restrict__ logvar,
                    const float* __restrict__ eps,
                    bf16* __restrict__ Zh, bf16* __restrict__ Zl, int n2) {
    int i = blockIdx.x * blockDim.x + threadIdx.x;
    if (i >= n2) return;
    float2 m  = reinterpret_cast<const float2*>(mu)[i];
    float2 lv = reinterpret_cast<const float2*>(logvar)[i];
    float2 e  = reinterpret_cast<const float2*>(eps)[i];
    float z0 = fmaf(e.x, expf(0.5f * lv.x), m.x);
    float z1 = fmaf(e.y, expf(0.5f * lv.y), m.y);
    bf16 h0, h1, l0, l1;
    split_bf16(z0, h0, l0);
    split_bf16(z1, h1, l1);
    __nv_bfloat162 ph = __halves2bfloat162(h0, h1);
    __nv_bfloat162 pl = __halves2bfloat162(l0, l1);
    reinterpret_cast<uint32_t*>(Zh)[i] = *reinterpret_cast<uint32_t*>(&ph);
    reinterpret_cast<uint32_t*>(Zl)[i] = *reinterpret_cast<uint32_t*>(&pl);
}

// ---------------------------------------------------------------------------
// Launcher
// ---------------------------------------------------------------------------
extern "C" void kernel_launch(void* const* d_in, const int* in_sizes, int n_in,
                              void* d_out, int out_size) {
    const float* x        = (const float*)d_in[0];
    const int*   labels   = (const int*)  d_in[1];
    const float* eps      = (const float*)d_in[2];
    const float* W_enc0   = (const float*)d_in[3];
    const float* b_enc0   = (const float*)d_in[4];
    const float* W_enc1   = (const float*)d_in[5];
    const float* b_enc1   = (const float*)d_in[6];
    const float* W_mu     = (const float*)d_in[7];
    const float* b_mu     = (const float*)d_in[8];
    const float* W_logvar = (const float*)d_in[9];
    const float* b_logvar = (const float*)d_in[10];
    const float* W_dec0   = (const float*)d_in[11];
    const float* b_dec0   = (const float*)d_in[12];
    const float* W_dec1   = (const float*)d_in[13];
    const float* b_dec1   = (const float*)d_in[14];
    const float* W_out    = (const float*)d_in[15];
    const float* b_out    = (const float*)d_in[16];

    float* recon  = (float*)d_out;
    float* mu     = recon + (size_t)BSZ * DIN;
    float* logvar = mu    + (size_t)BSZ * LATD;

    bf16 *xh, *xl, *w0t, *w1t, *wmut, *wlvt, *wd0t, *wd1t, *wot;
    bf16 *h0h, *h0l, *d0h, *d0l, *zh, *zl;
    cudaGetSymbolAddress((void**)&xh,  g_xh);   cudaGetSymbolAddress((void**)&xl,  g_xl);
    cudaGetSymbolAddress((void**)&w0t, g_w0t);  cudaGetSymbolAddress((void**)&w1t, g_w1t);
    cudaGetSymbolAddress((void**)&wmut, g_wmut); cudaGetSymbolAddress((void**)&wlvt, g_wlvt);
    cudaGetSymbolAddress((void**)&wd0t, g_wd0t); cudaGetSymbolAddress((void**)&wd1t, g_wd1t);
    cudaGetSymbolAddress((void**)&wot, g_wot);
    cudaGetSymbolAddress((void**)&h0h, g_h0h);  cudaGetSymbolAddress((void**)&h0l, g_h0l);
    cudaGetSymbolAddress((void**)&d0h, g_d0h);  cudaGetSymbolAddress((void**)&d0l, g_d0l);
    cudaGetSymbolAddress((void**)&zh,  g_zh);   cudaGetSymbolAddress((void**)&zl,  g_zl);

    cudaFuncSetAttribute(tc_gemm_k<true,  true,  1>,
                         cudaFuncAttributeMaxDynamicSharedMemorySize, TC_SMEM_TOTAL);
    cudaFuncSetAttribute(tc_gemm_k<true,  false, 1>,
                         cudaFuncAttributeMaxDynamicSharedMemorySize, TC_SMEM_TOTAL);
    cudaFuncSetAttribute(tc_gemm_k<false, false, 0>,
                         cudaFuncAttributeMaxDynamicSharedMemorySize, TC_SMEM_TOTAL);

    // 1. routing
    reset_counts_k<<<1, 32>>>();
    scatter_k<<<BSZ / 256, 256>>>(labels);

    // 2. conversions (weights -> tiled hi/lo pairs; x -> hi/lo row-major)
    convert_act_k<<<(BSZ * DIN / 4) / 256, 256>>>(x, xh, xl, BSZ * DIN / 4);
    convert_wt_k<<<dim3(H0D / 32, DIN / 32, NC), dim3(32, 8)>>>(W_enc0, w0t, DIN, H0D);
    convert_wt_k<<<dim3(H1D / 32, H0D / 32, 1), dim3(32, 8)>>>(W_enc1, w1t, H0D, H1D);
    convert_wt_k<<<dim3(LATD / 32, H1D / 32, 1), dim3(32, 8)>>>(W_mu, wmut, H1D, LATD);
    convert_wt_k<<<dim3(LATD / 32, H1D / 32, 1), dim3(32, 8)>>>(W_logvar, wlvt, H1D, LATD);
    convert_wt_k<<<dim3(H1D / 32, LATD / 32, 1), dim3(32, 8)>>>(W_dec0, wd0t, LATD, H1D);
    convert_wt_k<<<dim3(H0D / 32, H1D / 32, NC), dim3(32, 8)>>>(W_dec1, wd1t, H1D, H0D);
    convert_wt_k<<<dim3(DIN / 32, H0D / 32, 1), dim3(32, 8)>>>(W_out, wot, H0D, DIN);

    // 3. enc0 (grouped): h0 = relu(x @ W_enc0[c] + b) -> bf16 hi/lo
    tc_gemm_k<true, true, 1><<<dim3(H0D / TC_BN, BSZ / TC_BM, NC), TC_THREADS, TC_SMEM_TOTAL>>>(
        xh, xl, w0t, b_enc0, nullptr, h0h, h0l, BSZ, H0D, DIN);

    // 4. enc1: h1 = relu(h0 @ W_enc1 + b) -> bf16 hi/lo (into d0 buffers)
    tc_gemm_k<true, false, 1><<<dim3(H1D / TC_BN, BSZ / TC_BM, 1), TC_THREADS, TC_SMEM_TOTAL>>>(
        h0h, h0l, w1t, b_enc1, nullptr, d0h, d0l, BSZ, H1D, H0D);

    // 5. heads: mu / logvar (tc, fp32 straight into d_out)
    tc_gemm_k<false, false, 0><<<dim3(LATD / TC_BN, BSZ / TC_BM, 1), TC_THREADS, TC_SMEM_TOTAL>>>(
        d0h, d0l, wmut, b_mu, mu, nullptr, nullptr, BSZ, LATD, H1D);
    tc_gemm_k<false, false, 0><<<dim3(LATD / TC_BN, BSZ / TC_BM, 1), TC_THREADS, TC_SMEM_TOTAL>>>(
        d0h, d0l, wlvt, b_logvar, logvar, nullptr, nullptr, BSZ, LATD, H1D);

    // 6. reparameterize -> z hi/lo
    z_k<<<(BSZ * LATD / 2) / 256, 256>>>(mu, logvar, eps, zh, zl, BSZ * LATD / 2);

    // 7. dec0: d0 = relu(z @ W_dec0 + b) -> bf16 hi/lo
    tc_gemm_k<true, false, 1><<<dim3(H1D / TC_BN, BSZ / TC_BM, 1), TC_THREADS, TC_SMEM_TOTAL>>>(
        zh, zl, wd0t, b_dec0, nullptr, d0h, d0l, BSZ, H1D, LATD);

    // 8. dec1 (grouped): d1 = relu(d0 @ W_dec1[c] + b) -> bf16 hi/lo (reuse h0 bufs)
    tc_gemm_k<true, true, 1><<<dim3(H0D / TC_BN, BSZ / TC_BM, NC), TC_THREADS, TC_SMEM_TOTAL>>>(
        d0h, d0l, wd1t, b_dec1, nullptr, h0h, h0l, BSZ, H0D, H1D);

    // 9. out: recon = d1 @ W_out + b -> fp32
    tc_gemm_k<false, false, 0><<<dim3(DIN / TC_BN, BSZ / TC_BM, 1), TC_THREADS, TC_SMEM_TOTAL>>>(
        h0h, h0l, wot, b_out, recon, nullptr, nullptr, BSZ, DIN, H0D);
}

// round 13
// speedup vs baseline: 1.2240x; 1.2240x over previous
#include <cuda_runtime.h>
#include <cuda_bf16.h>
#include <cuda_fp16.h>
#include <cstdint>
#include <math.h>

// ---------------------------------------------------------------------------
// Problem constants
// ---------------------------------------------------------------------------
#define BSZ   8192
#define DIN   2048
#define H0D   1024
#define H1D   512
#define LATD  128
#define NC    8

typedef __nv_bfloat16 bf16;

// ---------------------------------------------------------------------------
// Scratch (device globals)
// ---------------------------------------------------------------------------
// fp16 path (enc0, out layers)
__device__ __half g_xhf[(size_t)BSZ * DIN];      // x hi (fp16)
__device__ __half g_xlf[(size_t)BSZ * DIN];      // x lo (fp16)
__device__ __half g_w0f[(size_t)NC * H0D * DIN]; // enc0^T fp16 single
__device__ __half g_wof[(size_t)DIN * H0D];      // out^T fp16 single
__device__ __half g_e1h[(size_t)BSZ * H0D];      // d1 hi (fp16)
__device__ __half g_e1l[(size_t)BSZ * H0D];      // d1 lo (fp16)
// bf16 path (enc1, mu, logvar, dec0, dec1)
__device__ bf16 g_w1h[(size_t)H1D * H0D];
__device__ bf16 g_w1l[(size_t)H1D * H0D];
__device__ bf16 g_wmuh[(size_t)LATD * H1D];
__device__ bf16 g_wmul[(size_t)LATD * H1D];
__device__ bf16 g_wlvh[(size_t)LATD * H1D];
__device__ bf16 g_wlvl[(size_t)LATD * H1D];
__device__ bf16 g_wd0h[(size_t)H1D * LATD];
__device__ bf16 g_wd0l[(size_t)H1D * LATD];
__device__ bf16 g_wd1h[(size_t)NC * H0D * H1D];
__device__ bf16 g_wd1l[(size_t)NC * H0D * H1D];
__device__ bf16 g_h0h[(size_t)BSZ * H0D];        // enc0 out (bf16 hi/lo)
__device__ bf16 g_h0l[(size_t)BSZ * H0D];
__device__ bf16 g_d0h[(size_t)BSZ * H1D];        // h1 / d0 (bf16 hi/lo)
__device__ bf16 g_d0l[(size_t)BSZ * H1D];
__device__ bf16 g_zh [(size_t)BSZ * LATD];
__device__ bf16 g_zl [(size_t)BSZ * LATD];
__device__ int   g_perm[NC * BSZ];
__device__ int   g_counts[NC];

// ---------------------------------------------------------------------------
// Routing
// ---------------------------------------------------------------------------
__global__ void reset_counts_k() {
    if (threadIdx.x < NC) g_counts[threadIdx.x] = 0;
}
__global__ void scatter_k(const int* __restrict__ labels) {
    int b = blockIdx.x * blockDim.x + threadIdx.x;
    if (b < BSZ) {
        int c = labels[b];
        int p = atomicAdd(&g_counts[c], 1);
        g_perm[c * BSZ + p] = b;
    }
}

// ---------------------------------------------------------------------------
// split helpers
// ---------------------------------------------------------------------------
__device__ __forceinline__ void split_bf16(float v, bf16& h, bf16& l) {
    h = __float2bfloat16_rn(v);
    l = __float2bfloat16_rn(v - __bfloat162float(h));
}
__device__ __forceinline__ void split_f16(float v, __half& h, __half& l) {
    h = __float2half_rn(v);
    l = __float2half_rn(v - __half2float(h));
}

// x -> fp16 hi/lo
__global__ void convert_act_f16_k(const float* __restrict__ X,
                                  __half* __restrict__ H, __half* __restrict__ L,
                                  int n4) {
    int i = blockIdx.x * blockDim.x + threadIdx.x;
    if (i >= n4) return;
    float4 v = reinterpret_cast<const float4*>(X)[i];
    __half h0, h1, h2, h3, l0, l1, l2, l3;
    split_f16(v.x, h0, l0); split_f16(v.y, h1, l1);
    split_f16(v.z, h2, l2); split_f16(v.w, h3, l3);
    __half2 ph0 = __halves2half2(h0, h1), ph1 = __halves2half2(h2, h3);
    __half2 pl0 = __halves2half2(l0, l1), pl1 = __halves2half2(l2, l3);
    uint2 uh = make_uint2(*(uint32_t*)&ph0, *(uint32_t*)&ph1);
    uint2 ul = make_uint2(*(uint32_t*)&pl0, *(uint32_t*)&pl1);
    *reinterpret_cast<uint2*>(H + (size_t)i * 4) = uh;
    *reinterpret_cast<uint2*>(L + (size_t)i * 4) = ul;
}

// Weight convert+transpose: W [K,N] fp32 -> Th/Tl [N,K] bf16 hi/lo. grid.z = group.
__global__ void convert_wt_k(const float* __restrict__ W,
                             bf16* __restrict__ Th, bf16* __restrict__ Tl,
                             int K, int N) {
    __shared__ float tile[32][33];
    int g = blockIdx.z;
    const float* Wg = W + (size_t)g * K * N;
    bf16* Thg = Th + (size_t)g * N * K;
    bf16* Tlg = Tl + (size_t)g * N * K;
    int n0 = blockIdx.x * 32, k0 = blockIdx.y * 32;
    int tx = threadIdx.x, ty = threadIdx.y;
    #pragma unroll
    for (int i = 0; i < 4; i++)
        tile[ty + 8 * i][tx] = Wg[(size_t)(k0 + ty + 8 * i) * N + n0 + tx];
    __syncthreads();
    #pragma unroll
    for (int i = 0; i < 4; i++) {
        float v = tile[tx][ty + 8 * i];
        bf16 h, l;
        split_bf16(v, h, l);
        size_t o = (size_t)(n0 + ty + 8 * i) * K + k0 + tx;
        Thg[o] = h;
        Tlg[o] = l;
    }
}

// Weight convert+transpose: W [K,N] fp32 -> T [N,K] fp16 single. grid.z = group.
__global__ void convert_wtf_k(const float* __restrict__ W,
                              __half* __restrict__ T, int K, int N) {
    __shared__ float tile[32][33];
    int g = blockIdx.z;
    const float* Wg = W + (size_t)g * K * N;
    __half* Tg = T + (size_t)g * N * K;
    int n0 = blockIdx.x * 32, k0 = blockIdx.y * 32;
    int tx = threadIdx.x, ty = threadIdx.y;
    #pragma unroll
    for (int i = 0; i < 4; i++)
        tile[ty + 8 * i][tx] = Wg[(size_t)(k0 + ty + 8 * i) * N + n0 + tx];
    __syncthreads();
    #pragma unroll
    for (int i = 0; i < 4; i++) {
        float v = tile[tx][ty + 8 * i];
        Tg[(size_t)(n0 + ty + 8 * i) * K + k0 + tx] = __float2half_rn(v);
    }
}

// ---------------------------------------------------------------------------
// PTX wrappers
// ---------------------------------------------------------------------------
__device__ __forceinline__ uint32_t smem_u32(const void* p) {
    uint32_t a;
    asm("{ .reg .u64 t; cvta.to.shared.u64 t, %1; cvt.u32.u64 %0, t; }"
        : "=r"(a) : "l"(p));
    return a;
}

__device__ __forceinline__ void cp_async16(uint32_t saddr, const void* g, bool ok) {
    int sz = ok ? 16 : 0;
    asm volatile("cp.async.cg.shared.global [%0], [%1], 16, %2;"
                 :: "r"(saddr), "l"(g), "r"(sz));
}
#define CP_COMMIT() asm volatile("cp.async.commit_group;" ::: "memory")
#define CP_WAIT(n)  asm volatile("cp.async.wait_group %0;" :: "n"(n) : "memory")

__device__ __forceinline__ void ldsm_x4(uint32_t* r, uint32_t addr) {
    asm volatile("ldmatrix.sync.aligned.m8n8.x4.shared.b16 {%0,%1,%2,%3}, [%4];"
                 : "=r"(r[0]), "=r"(r[1]), "=r"(r[2]), "=r"(r[3]) : "r"(addr));
}

__device__ __forceinline__ void mma_bf16(float* c, const uint32_t* a, const uint32_t* b) {
    asm volatile(
        "mma.sync.aligned.m16n8k16.row.col.f32.bf16.bf16.f32 "
        "{%0,%1,%2,%3}, {%4,%5,%6,%7}, {%8,%9}, {%0,%1,%2,%3};"
        : "+f"(c[0]), "+f"(c[1]), "+f"(c[2]), "+f"(c[3])
        : "r"(a[0]), "r"(a[1]), "r"(a[2]), "r"(a[3]), "r"(b[0]), "r"(b[1]));
}
__device__ __forceinline__ void mma_f16(float* c, const uint32_t* a, const uint32_t* b) {
    asm volatile(
        "mma.sync.aligned.m16n8k16.row.col.f32.f16.f16.f32 "
        "{%0,%1,%2,%3}, {%4,%5,%6,%7}, {%8,%9}, {%0,%1,%2,%3};"
        : "+f"(c[0]), "+f"(c[1]), "+f"(c[2]), "+f"(c[3])
        : "r"(a[0]), "r"(a[1]), "r"(a[2]), "r"(a[3]), "r"(b[0]), "r"(b[1]));
}

// ---------------------------------------------------------------------------
// mma.sync GEMM: 256x128x32 CTA tile, 3-stage cp.async pipeline.
// MMAT 0: bf16x3 split (A hi/lo, B hi/lo; passes hh, hl, lh).
// MMAT 1: fp16x2 split (A hi/lo fp16, B single fp16; passes h, l).
// smem rows: 32 elems = 64B tight, XOR chunk swizzle c' = v ^ ((row>>1)&3).
// ---------------------------------------------------------------------------
#define TC_BM 256
#define TC_BN 128
#define TC_KC 32
#define TC_THREADS 512
#define TC_NSTAGE 3
#define A_TILE_B (TC_BM * 64)          // 16384
#define B_TILE_B (TC_BN * 64)          // 8192

__device__ __forceinline__ uint32_t swz_off(int row, int v) {
    return (uint32_t)(row * 64 + ((v ^ ((row >> 1) & 3)) << 4));
}

template <bool GROUPED, int MMAT>
__device__ __forceinline__ void tc_load_stage(
    uint32_t stage_base, const int* __restrict__ rows, int tid, int k0,
    const uint16_t* __restrict__ Ah, const uint16_t* __restrict__ Al,
    const uint16_t* __restrict__ Bh, const uint16_t* __restrict__ Bl,
    int m0, int n0, int K)
{
    constexpr int NT = MMAT ? 5 : 6;   // 2560 or 3072 16B ops
    #pragma unroll
    for (int t = 0; t < NT; t++) {
        int idx = tid + t * TC_THREADS;
        if (idx < 2048) {
            int tile = idx >> 10;
            int rem  = idx & 1023;
            int row  = rem >> 2;
            int v    = rem & 3;
            int gr = GROUPED ? rows[row] : (m0 + row);
            bool ok = !GROUPED || (gr >= 0);
            const uint16_t* src = tile ? Al : Ah;
            cp_async16(stage_base + tile * A_TILE_B + swz_off(row, v),
                       src + ((size_t)(ok ? gr : 0) * K + k0 + v * 8), ok);
        } else if (MMAT == 0) {
            int j    = idx - 2048;
            int tile = j >> 9;
            int rem  = j & 511;
            int row  = rem >> 2;
            int v    = rem & 3;
            const uint16_t* src = tile ? Bl : Bh;
            cp_async16(stage_base + 2 * A_TILE_B + tile * B_TILE_B + swz_off(row, v),
                       src + ((size_t)(n0 + row) * K + k0 + v * 8), true);
        } else {
            int j   = idx - 2048;      // 0..511
            int row = j >> 2;
            int v   = j & 3;
            cp_async16(stage_base + 2 * A_TILE_B + swz_off(row, v),
                       Bh + ((size_t)(n0 + row) * K + k0 + v * 8), true);
        }
    }
}

// OUTMODE: 0 = fp32, 1 = bf16 hi/lo, 2 = fp16 hi/lo
template <bool RELU, bool GROUPED, int OUTMODE, int MMAT>
__global__ void __launch_bounds__(TC_THREADS, 1)
tc_gemm_k(const uint16_t* __restrict__ Ah, const uint16_t* __restrict__ Al,
          const uint16_t* __restrict__ Bhg, const uint16_t* __restrict__ Blg,
          const float* __restrict__ biasg,
          float* __restrict__ OutF,
          uint16_t* __restrict__ Oh, uint16_t* __restrict__ Ol,
          int M, int N, int K)
{
    constexpr int STAGE = MMAT ? (2 * A_TILE_B + B_TILE_B)
                               : (2 * A_TILE_B + 2 * B_TILE_B);
    constexpr int ROWS_OFF = TC_NSTAGE * STAGE;

    extern __shared__ char smem[];
    const int tid  = threadIdx.x;
    const int wid  = tid >> 5;
    const int lane = tid & 31;
    const int wm   = wid >> 2;
    const int wn   = wid & 3;
    const int g    = GROUPED ? blockIdx.z : 0;
    const int m0   = blockIdx.y * TC_BM;
    if (GROUPED) {
        if (m0 >= g_counts[g]) return;
    }
    const int n0 = blockIdx.x * TC_BN;
    uint32_t sb = smem_u32(smem);
    int* rows_s = reinterpret_cast<int*>(smem + ROWS_OFF);

    if (GROUPED) {
        if (tid < TC_BM) {
            int cnt = g_counts[g];
            int r = m0 + tid;
            rows_s[tid] = (r < cnt) ? g_perm[g * BSZ + r] : -1;
        }
        __syncthreads();
    }

    const uint16_t* Bh = Bhg + (GROUPED ? (size_t)g * N * K : 0);
    const uint16_t* Bl = (MMAT == 0) ? (Blg + (GROUPED ? (size_t)g * N * K : 0))
                                     : nullptr;

    float acc[4][4][4];
    #pragma unroll
    for (int i = 0; i < 4; i++)
        #pragma unroll
        for (int j = 0; j < 4; j++)
            #pragma unroll
            for (int q = 0; q < 4; q++) acc[i][j][q] = 0.f;

    const int nchunks = K / TC_KC;

    tc_load_stage<GROUPED, MMAT>(sb + 0 * STAGE, rows_s, tid, 0,
                                 Ah, Al, Bh, Bl, m0, n0, K);
    CP_COMMIT();
    tc_load_stage<GROUPED, MMAT>(sb + 1 * STAGE, rows_s, tid, TC_KC,
                                 Ah, Al, Bh, Bl, m0, n0, K);
    CP_COMMIT();

    int stage = 0;
    for (int i = 0; i < nchunks; i++) {
        if (i + 1 < nchunks) { CP_WAIT(1); } else { CP_WAIT(0); }
        __syncthreads();

        if (i + 2 < nchunks) {
            int ps = stage + 2; if (ps >= TC_NSTAGE) ps -= TC_NSTAGE;
            tc_load_stage<GROUPED, MMAT>(sb + ps * STAGE, rows_s, tid,
                                         (i + 2) * TC_KC, Ah, Al, Bh, Bl, m0, n0, K);
            CP_COMMIT();
        }

        uint32_t st = sb + stage * STAGE;
        #pragma unroll
        for (int kk = 0; kk < 2; kk++) {
            const int vb = kk * 2 + (lane >> 4);
            uint32_t bhf[8], blf[8];
            #pragma unroll
            for (int p = 0; p < 2; p++) {
                int brow = wn * 32 + p * 16 + (lane & 15);
                uint32_t r[4];
                ldsm_x4(r, st + 2 * A_TILE_B + swz_off(brow, vb));
                bhf[4 * p + 0] = r[0]; bhf[4 * p + 1] = r[2];
                bhf[4 * p + 2] = r[1]; bhf[4 * p + 3] = r[3];
                if (MMAT == 0) {
                    ldsm_x4(r, st + 2 * A_TILE_B + B_TILE_B + swz_off(brow, vb));
                    blf[4 * p + 0] = r[0]; blf[4 * p + 1] = r[2];
                    blf[4 * p + 2] = r[1]; blf[4 * p + 3] = r[3];
                }
            }
            uint32_t a[4][4];
            #pragma unroll
            for (int mt = 0; mt < 4; mt++) {
                int arow = wm * 64 + mt * 16 + (lane & 15);
                ldsm_x4(a[mt], st + swz_off(arow, vb));
            }
            if (MMAT == 0) {
                #pragma unroll
                for (int mt = 0; mt < 4; mt++)
                    #pragma unroll
                    for (int nt = 0; nt < 4; nt++)
                        mma_bf16(acc[mt][nt], a[mt], &bhf[2 * nt]);
                #pragma unroll
                for (int mt = 0; mt < 4; mt++)
                    #pragma unroll
                    for (int nt = 0; nt < 4; nt++)
                        mma_bf16(acc[mt][nt], a[mt], &blf[2 * nt]);
            } else {
                #pragma unroll
                for (int mt = 0; mt < 4; mt++)
                    #pragma unroll
                    for (int nt = 0; nt < 4; nt++)
                        mma_f16(acc[mt][nt], a[mt], &bhf[2 * nt]);
            }
            // A lo fragments
            #pragma unroll
            for (int mt = 0; mt < 4; mt++) {
                int arow = wm * 64 + mt * 16 + (lane & 15);
                ldsm_x4(a[mt], st + A_TILE_B + swz_off(arow, vb));
            }
            if (MMAT == 0) {
                #pragma unroll
                for (int mt = 0; mt < 4; mt++)
                    #pragma unroll
                    for (int nt = 0; nt < 4; nt++)
                        mma_bf16(acc[mt][nt], a[mt], &bhf[2 * nt]);
            } else {
                #pragma unroll
                for (int mt = 0; mt < 4; mt++)
                    #pragma unroll
                    for (int nt = 0; nt < 4; nt++)
                        mma_f16(acc[mt][nt], a[mt], &bhf[2 * nt]);
            }
        }
        stage = stage + 1; if (stage >= TC_NSTAGE) stage = 0;
    }

    // Epilogue
    const float* bias = biasg + (GROUPED ? (size_t)g * N : 0);
    #pragma unroll
    for (int mt = 0; mt < 4; mt++) {
        #pragma unroll
        for (int half = 0; half < 2; half++) {
            int rloc = wm * 64 + mt * 16 + (lane >> 2) + half * 8;
            int gm = GROUPED ? rows_s[rloc] : (m0 + rloc);
            if (GROUPED && gm < 0) continue;
            #pragma unroll
            for (int nt = 0; nt < 4; nt++) {
                int col = n0 + wn * 32 + nt * 8 + 2 * (lane & 3);
                float c0 = acc[mt][nt][2 * half + 0] + bias[col];
                float c1 = acc[mt][nt][2 * half + 1] + bias[col + 1];
                if (RELU) { c0 = fmaxf(c0, 0.f); c1 = fmaxf(c1, 0.f); }
                if (OUTMODE == 0) {
                    *reinterpret_cast<float2*>(OutF + (size_t)gm * N + col) =
                        make_float2(c0, c1);
                } else if (OUTMODE == 1) {
                    bf16 h0, h1, l0, l1;
                    split_bf16(c0, h0, l0);
                    split_bf16(c1, h1, l1);
                    __nv_bfloat162 ph = __halves2bfloat162(h0, h1);
                    __nv_bfloat162 pl = __halves2bfloat162(l0, l1);
                    *reinterpret_cast<uint32_t*>(Oh + (size_t)gm * N + col) =
                        *reinterpret_cast<uint32_t*>(&ph);
                    *reinterpret_cast<uint32_t*>(Ol + (size_t)gm * N + col) =
                        *reinterpret_cast<uint32_t*>(&pl);
                } else {
                    __half h0, h1, l0, l1;
                    split_f16(c0, h0, l0);
                    split_f16(c1, h1, l1);
                    __half2 ph = __halves2half2(h0, h1);
                    __half2 pl = __halves2half2(l0, l1);
                    *reinterpret_cast<uint32_t*>(Oh + (size_t)gm * N + col) =
                        *reinterpret_cast<uint32_t*>(&ph);
                    *reinterpret_cast<uint32_t*>(Ol + (size_t)gm * N + col) =
                        *reinterpret_cast<uint32_t*>(&pl);
                }
            }
        }
    }
}

// ---------------------------------------------------------------------------
// Reparameterize + bf16 hi/lo split
// ---------------------------------------------------------------------------
__global__ void z_k(const float* __restrict__ mu, const float* __restrict__ logvar,
                    const float* __restrict__ eps,
                    bf16* __restrict__ Zh, bf16* __restrict__ Zl, int n2) {
    int i = blockIdx.x * blockDim.x + threadIdx.x;
    if (i >= n2) return;
    float2 m  = reinterpret_cast<const float2*>(mu)[i];
    float2 lv = reinterpret_cast<const float2*>(logvar)[i];
    float2 e  = reinterpret_cast<const float2*>(eps)[i];
    float z0 = fmaf(e.x, expf(0.5f * lv.x), m.x);
    float z1 = fmaf(e.y, expf(0.5f * lv.y), m.y);
    bf16 h0, h1, l0, l1;
    split_bf16(z0, h0, l0);
    split_bf16(z1, h1, l1);
    __nv_bfloat162 ph = __halves2bfloat162(h0, h1);
    __nv_bfloat162 pl = __halves2bfloat162(l0, l1);
    reinterpret_cast<uint32_t*>(Zh)[i] = *reinterpret_cast<uint32_t*>(&ph);
    reinterpret_cast<uint32_t*>(Zl)[i] = *reinterpret_cast<uint32_t*>(&pl);
}

// ---------------------------------------------------------------------------
// Launcher
// ---------------------------------------------------------------------------
#define SMEM_BF (TC_NSTAGE * (2 * A_TILE_B + 2 * B_TILE_B) + TC_BM * 4)
#define SMEM_F16 (TC_NSTAGE * (2 * A_TILE_B + B_TILE_B) + TC_BM * 4)

extern "C" void kernel_launch(void* const* d_in, const int* in_sizes, int n_in,
                              void* d_out, int out_size) {
    const float* x        = (const float*)d_in[0];
    const int*   labels   = (const int*)  d_in[1];
    const float* eps      = (const float*)d_in[2];
    const float* W_enc0   = (const float*)d_in[3];
    const float* b_enc0   = (const float*)d_in[4];
    const float* W_enc1   = (const float*)d_in[5];
    const float* b_enc1   = (const float*)d_in[6];
    const float* W_mu     = (const float*)d_in[7];
    const float* b_mu     = (const float*)d_in[8];
    const float* W_logvar = (const float*)d_in[9];
    const float* b_logvar = (const float*)d_in[10];
    const float* W_dec0   = (const float*)d_in[11];
    const float* b_dec0   = (const float*)d_in[12];
    const float* W_dec1   = (const float*)d_in[13];
    const float* b_dec1   = (const float*)d_in[14];
    const float* W_out    = (const float*)d_in[15];
    const float* b_out    = (const float*)d_in[16];

    float* recon  = (float*)d_out;
    float* mu     = recon + (size_t)BSZ * DIN;
    float* logvar = mu    + (size_t)BSZ * LATD;

    uint16_t *xhf, *xlf, *w0f, *wof, *e1h, *e1l;
    uint16_t *w1h, *w1l, *wmuh, *wmul, *wlvh, *wlvl, *wd0h, *wd0l, *wd1h, *wd1l;
    uint16_t *h0h, *h0l, *d0h, *d0l, *zh, *zl;
    cudaGetSymbolAddress((void**)&xhf, g_xhf);  cudaGetSymbolAddress((void**)&xlf, g_xlf);
    cudaGetSymbolAddress((void**)&w0f, g_w0f);  cudaGetSymbolAddress((void**)&wof, g_wof);
    cudaGetSymbolAddress((void**)&e1h, g_e1h);  cudaGetSymbolAddress((void**)&e1l, g_e1l);
    cudaGetSymbolAddress((void**)&w1h, g_w1h);  cudaGetSymbolAddress((void**)&w1l, g_w1l);
    cudaGetSymbolAddress((void**)&wmuh, g_wmuh); cudaGetSymbolAddress((void**)&wmul, g_wmul);
    cudaGetSymbolAddress((void**)&wlvh, g_wlvh); cudaGetSymbolAddress((void**)&wlvl, g_wlvl);
    cudaGetSymbolAddress((void**)&wd0h, g_wd0h); cudaGetSymbolAddress((void**)&wd0l, g_wd0l);
    cudaGetSymbolAddress((void**)&wd1h, g_wd1h); cudaGetSymbolAddress((void**)&wd1l, g_wd1l);
    cudaGetSymbolAddress((void**)&h0h, g_h0h);  cudaGetSymbolAddress((void**)&h0l, g_h0l);
    cudaGetSymbolAddress((void**)&d0h, g_d0h);  cudaGetSymbolAddress((void**)&d0l, g_d0l);
    cudaGetSymbolAddress((void**)&zh,  g_zh);   cudaGetSymbolAddress((void**)&zl,  g_zl);

    cudaFuncSetAttribute(tc_gemm_k<true,  true,  1, 1>,
                         cudaFuncAttributeMaxDynamicSharedMemorySize, SMEM_F16);
    cudaFuncSetAttribute(tc_gemm_k<false, false, 0, 1>,
                         cudaFuncAttributeMaxDynamicSharedMemorySize, SMEM_F16);
    cudaFuncSetAttribute(tc_gemm_k<true,  false, 1, 0>,
                         cudaFuncAttributeMaxDynamicSharedMemorySize, SMEM_BF);
    cudaFuncSetAttribute(tc_gemm_k<false, false, 0, 0>,
                         cudaFuncAttributeMaxDynamicSharedMemorySize, SMEM_BF);
    cudaFuncSetAttribute(tc_gemm_k<true,  true,  2, 0>,
                         cudaFuncAttributeMaxDynamicSharedMemorySize, SMEM_BF);

    // 1. routing
    reset_counts_k<<<1, 32>>>();
    scatter_k<<<BSZ / 256, 256>>>(labels);

    // 2. conversions
    convert_act_f16_k<<<(BSZ * DIN / 4) / 256, 256>>>(x, (__half*)xhf, (__half*)xlf,
                                                      BSZ * DIN / 4);
    convert_wtf_k<<<dim3(H0D / 32, DIN / 32, NC), dim3(32, 8)>>>(W_enc0, (__half*)w0f, DIN, H0D);
    convert_wt_k<<<dim3(H1D / 32, H0D / 32, 1), dim3(32, 8)>>>(W_enc1, (bf16*)w1h, (bf16*)w1l, H0D, H1D);
    convert_wt_k<<<dim3(LATD / 32, H1D / 32, 1), dim3(32, 8)>>>(W_mu, (bf16*)wmuh, (bf16*)wmul, H1D, LATD);
    convert_wt_k<<<dim3(LATD / 32, H1D / 32, 1), dim3(32, 8)>>>(W_logvar, (bf16*)wlvh, (bf16*)wlvl, H1D, LATD);
    convert_wt_k<<<dim3(H1D / 32, LATD / 32, 1), dim3(32, 8)>>>(W_dec0, (bf16*)wd0h, (bf16*)wd0l, LATD, H1D);
    convert_wt_k<<<dim3(H0D / 32, H1D / 32, NC), dim3(32, 8)>>>(W_dec1, (bf16*)wd1h, (bf16*)wd1l, H1D, H0D);
    convert_wtf_k<<<dim3(DIN / 32, H0D / 32, 1), dim3(32, 8)>>>(W_out, (__half*)wof, H0D, DIN);

    // 3. enc0 (grouped, fp16x2): h0 = relu(x @ W_enc0[c] + b) -> bf16 hi/lo
    tc_gemm_k<true, true, 1, 1><<<dim3(H0D / TC_BN, BSZ / TC_BM, NC), TC_THREADS, SMEM_F16>>>(
        xhf, xlf, w0f, nullptr, b_enc0, nullptr, h0h, h0l, BSZ, H0D, DIN);

    // 4. enc1 (bf16x3): h1 = relu(h0 @ W_enc1 + b) -> bf16 hi/lo (d0 bufs)
    tc_gemm_k<true, false, 1, 0><<<dim3(H1D / TC_BN, BSZ / TC_BM, 1), TC_THREADS, SMEM_BF>>>(
        h0h, h0l, w1h, w1l, b_enc1, nullptr, d0h, d0l, BSZ, H1D, H0D);

    // 5. heads (bf16x3, fp32 straight into d_out)
    tc_gemm_k<false, false, 0, 0><<<dim3(LATD / TC_BN, BSZ / TC_BM, 1), TC_THREADS, SMEM_BF>>>(
        d0h, d0l, wmuh, wmul, b_mu, mu, nullptr, nullptr, BSZ, LATD, H1D);
    tc_gemm_k<false, false, 0, 0><<<dim3(LATD / TC_BN, BSZ / TC_BM, 1), TC_THREADS, SMEM_BF>>>(
        d0h, d0l, wlvh, wlvl, b_logvar, logvar, nullptr, nullptr, BSZ, LATD, H1D);

    // 6. reparameterize -> z bf16 hi/lo
    z_k<<<(BSZ * LATD / 2) / 256, 256>>>(mu, logvar, eps, (bf16*)zh, (bf16*)zl,
                                         BSZ * LATD / 2);

    // 7. dec0 (bf16x3): d0 = relu(z @ W_dec0 + b) -> bf16 hi/lo
    tc_gemm_k<true, false, 1, 0><<<dim3(H1D / TC_BN, BSZ / TC_BM, 1), TC_THREADS, SMEM_BF>>>(
        zh, zl, wd0h, wd0l, b_dec0, nullptr, d0h, d0l, BSZ, H1D, LATD);

    // 8. dec1 (grouped, bf16x3): d1 = relu(d0 @ W_dec1[c] + b) -> fp16 hi/lo
    tc_gemm_k<true, true, 2, 0><<<dim3(H0D / TC_BN, BSZ / TC_BM, NC), TC_THREADS, SMEM_BF>>>(
        d0h, d0l, wd1h, wd1l, b_dec1, nullptr, e1h, e1l, BSZ, H0D, H1D);

    // 9. out (fp16x2): recon = d1 @ W_out + b -> fp32
    tc_gemm_k<false, false, 0, 1><<<dim3(DIN / TC_BN, BSZ / TC_BM, 1), TC_THREADS, SMEM_F16>>>(
        e1h, e1l, wof, nullptr, b_out, recon, nullptr, nullptr, BSZ, DIN, H0D);
}

// round 15
// speedup vs baseline: 1.9394x; 1.5845x over previous
#include <cuda_runtime.h>
#include <cuda_fp16.h>
#include <cstdint>
#include <math.h>

// ---------------------------------------------------------------------------
// Problem constants
// ---------------------------------------------------------------------------
#define BSZ   8192
#define DIN   2048
#define H0D   1024
#define H1D   512
#define LATD  128
#define NC    8

// ---------------------------------------------------------------------------
// Scratch (device globals) — all fp16
// ---------------------------------------------------------------------------
__device__ __half g_xh [(size_t)BSZ * DIN];       // x hi
__device__ __half g_xl [(size_t)BSZ * DIN];       // x lo
__device__ __half g_w0 [(size_t)NC * H0D * DIN];  // enc0^T [C, H0, DIN]
__device__ __half g_w1 [(size_t)H1D * H0D];       // enc1^T
__device__ __half g_wmulv[(size_t)2 * LATD * H1D];// [mu^T ; logvar^T] 256 x H1
__device__ __half g_wd0[(size_t)H1D * LATD];      // dec0^T
__device__ __half g_wd1[(size_t)NC * H0D * H1D];  // dec1^T
__device__ __half g_wo [(size_t)DIN * H0D];       // out^T
__device__ __half g_h0h[(size_t)BSZ * H0D];       // h0 / d1 hi
__device__ __half g_h0l[(size_t)BSZ * H0D];       // h0 / d1 lo
__device__ __half g_h1h[(size_t)BSZ * H1D];       // h1 / d0 hi
__device__ __half g_h1l[(size_t)BSZ * H1D];       // h1 / d0 lo
__device__ __half g_zh [(size_t)BSZ * LATD];
__device__ __half g_zl [(size_t)BSZ * LATD];
__device__ int    g_perm[NC * BSZ];
__device__ int    g_counts[NC];

// ---------------------------------------------------------------------------
// Routing
// ---------------------------------------------------------------------------
__global__ void reset_counts_k() {
    if (threadIdx.x < NC) g_counts[threadIdx.x] = 0;
}
__global__ void scatter_k(const int* __restrict__ labels) {
    int b = blockIdx.x * blockDim.x + threadIdx.x;
    if (b < BSZ) {
        int c = labels[b];
        int p = atomicAdd(&g_counts[c], 1);
        g_perm[c * BSZ + p] = b;
    }
}

// ---------------------------------------------------------------------------
// split helper
// ---------------------------------------------------------------------------
__device__ __forceinline__ void split_f16(float v, __half& h, __half& l) {
    h = __float2half_rn(v);
    l = __float2half_rn(v - __half2float(h));
}

// x -> fp16 hi/lo
__global__ void convert_act_k(const float* __restrict__ X,
                              __half* __restrict__ H, __half* __restrict__ L,
                              int n4) {
    int i = blockIdx.x * blockDim.x + threadIdx.x;
    if (i >= n4) return;
    float4 v = reinterpret_cast<const float4*>(X)[i];
    __half h0, h1, h2, h3, l0, l1, l2, l3;
    split_f16(v.x, h0, l0); split_f16(v.y, h1, l1);
    split_f16(v.z, h2, l2); split_f16(v.w, h3, l3);
    __half2 ph0 = __halves2half2(h0, h1), ph1 = __halves2half2(h2, h3);
    __half2 pl0 = __halves2half2(l0, l1), pl1 = __halves2half2(l2, l3);
    uint2 uh = make_uint2(*(uint32_t*)&ph0, *(uint32_t*)&ph1);
    uint2 ul = make_uint2(*(uint32_t*)&pl0, *(uint32_t*)&pl1);
    *reinterpret_cast<uint2*>(H + (size_t)i * 4) = uh;
    *reinterpret_cast<uint2*>(L + (size_t)i * 4) = ul;
}

// Weight convert+transpose: W [K,N] fp32 -> T [N,K] fp16. grid.z = group.
__global__ void convert_wt_k(const float* __restrict__ W,
                             __half* __restrict__ T, int K, int N) {
    __shared__ float tile[32][33];
    int g = blockIdx.z;
    const float* Wg = W + (size_t)g * K * N;
    __half* Tg = T + (size_t)g * N * K;
    int n0 = blockIdx.x * 32, k0 = blockIdx.y * 32;
    int tx = threadIdx.x, ty = threadIdx.y;
    #pragma unroll
    for (int i = 0; i < 4; i++)
        tile[ty + 8 * i][tx] = Wg[(size_t)(k0 + ty + 8 * i) * N + n0 + tx];
    __syncthreads();
    #pragma unroll
    for (int i = 0; i < 4; i++) {
        float v = tile[tx][ty + 8 * i];
        Tg[(size_t)(n0 + ty + 8 * i) * K + k0 + tx] = __float2half_rn(v);
    }
}

// ---------------------------------------------------------------------------
// PTX wrappers
// ---------------------------------------------------------------------------
__device__ __forceinline__ uint32_t smem_u32(const void* p) {
    uint32_t a;
    asm("{ .reg .u64 t; cvta.to.shared.u64 t, %1; cvt.u32.u64 %0, t; }"
        : "=r"(a) : "l"(p));
    return a;
}

__device__ __forceinline__ void cp_async16(uint32_t saddr, const void* g, bool ok) {
    int sz = ok ? 16 : 0;
    asm volatile("cp.async.cg.shared.global [%0], [%1], 16, %2;"
                 :: "r"(saddr), "l"(g), "r"(sz));
}
#define CP_COMMIT() asm volatile("cp.async.commit_group;" ::: "memory")
#define CP_WAIT(n)  asm volatile("cp.async.wait_group %0;" :: "n"(n) : "memory")

__device__ __forceinline__ void ldsm_x4(uint32_t* r, uint32_t addr) {
    asm volatile("ldmatrix.sync.aligned.m8n8.x4.shared.b16 {%0,%1,%2,%3}, [%4];"
                 : "=r"(r[0]), "=r"(r[1]), "=r"(r[2]), "=r"(r[3]) : "r"(addr));
}

__device__ __forceinline__ void mma_f16(float* c, const uint32_t* a, const uint32_t* b) {
    asm volatile(
        "mma.sync.aligned.m16n8k16.row.col.f32.f16.f16.f32 "
        "{%0,%1,%2,%3}, {%4,%5,%6,%7}, {%8,%9}, {%0,%1,%2,%3};"
        : "+f"(c[0]), "+f"(c[1]), "+f"(c[2]), "+f"(c[3])
        : "r"(a[0]), "r"(a[1]), "r"(a[2]), "r"(a[3]), "r"(b[0]), "r"(b[1]));
}

// ---------------------------------------------------------------------------
// fp16 mma.sync GEMM: 256x128x32 CTA tile, 3-stage cp.async pipeline.
// PASSES=1: D = A_hi * B.   PASSES=2: D = A_hi * B + A_lo * B.
// B always single fp16. smem rows 64B, swizzle c' = v ^ ((row>>1)&3).
// OUTMODE: 0 = fp32, 2 = fp16 hi/lo, 3 = split fp32 (mu | logvar by n-block)
// ---------------------------------------------------------------------------
#define TC_BM 256
#define TC_BN 128
#define TC_KC 32
#define TC_THREADS 512
#define TC_NSTAGE 3
#define A_TILE_B (TC_BM * 64)          // 16384
#define B_TILE_B (TC_BN * 64)          // 8192

__device__ __forceinline__ uint32_t swz_off(int row, int v) {
    return (uint32_t)(row * 64 + ((v ^ ((row >> 1) & 3)) << 4));
}

template <bool GROUPED, int PASSES>
__device__ __forceinline__ void tc_load_stage(
    uint32_t stage_base, const int* __restrict__ rows, int tid, int k0,
    const __half* __restrict__ Ah, const __half* __restrict__ Al,
    const __half* __restrict__ B, int m0, int n0, int K)
{
    constexpr int A_OPS = PASSES * 1024;
    constexpr int NT = (A_OPS + 512) / TC_THREADS;  // 3 or 5
    #pragma unroll
    for (int t = 0; t < NT; t++) {
        int idx = tid + t * TC_THREADS;
        if (idx < A_OPS) {
            int tile = idx >> 10;
            int rem  = idx & 1023;
            int row  = rem >> 2;
            int v    = rem & 3;
            int gr = GROUPED ? rows[row] : (m0 + row);
            bool ok = !GROUPED || (gr >= 0);
            const __half* src = tile ? Al : Ah;
            cp_async16(stage_base + tile * A_TILE_B + swz_off(row, v),
                       src + ((size_t)(ok ? gr : 0) * K + k0 + v * 8), ok);
        } else {
            int j   = idx - A_OPS;     // 0..511
            int row = j >> 2;
            int v   = j & 3;
            cp_async16(stage_base + PASSES * A_TILE_B + swz_off(row, v),
                       B + ((size_t)(n0 + row) * K + k0 + v * 8), true);
        }
    }
}

template <bool RELU, bool GROUPED, int OUTMODE, int PASSES>
__global__ void __launch_bounds__(TC_THREADS, 1)
tc_gemm_k(const __half* __restrict__ Ah, const __half* __restrict__ Al,
          const __half* __restrict__ Bg,
          const float* __restrict__ biasg, const float* __restrict__ bias2,
          float* __restrict__ OutF, float* __restrict__ OutF2,
          __half* __restrict__ Oh, __half* __restrict__ Ol,
          int M, int N, int K)
{
    constexpr int STAGE = PASSES * A_TILE_B + B_TILE_B;
    constexpr int ROWS_OFF = TC_NSTAGE * STAGE;

    extern __shared__ char smem[];
    const int tid  = threadIdx.x;
    const int wid  = tid >> 5;
    const int lane = tid & 31;
    const int wm   = wid >> 2;
    const int wn   = wid & 3;
    const int g    = GROUPED ? blockIdx.z : 0;
    const int m0   = blockIdx.y * TC_BM;
    if (GROUPED) {
        if (m0 >= g_counts[g]) return;
    }
    const int n0 = blockIdx.x * TC_BN;
    uint32_t sb = smem_u32(smem);
    int* rows_s = reinterpret_cast<int*>(smem + ROWS_OFF);

    if (GROUPED) {
        if (tid < TC_BM) {
            int cnt = g_counts[g];
            int r = m0 + tid;
            rows_s[tid] = (r < cnt) ? g_perm[g * BSZ + r] : -1;
        }
        __syncthreads();
    }

    const __half* B = Bg + (GROUPED ? (size_t)g * N * K : 0);

    float acc[4][4][4];
    #pragma unroll
    for (int i = 0; i < 4; i++)
        #pragma unroll
        for (int j = 0; j < 4; j++)
            #pragma unroll
            for (int q = 0; q < 4; q++) acc[i][j][q] = 0.f;

    const int nchunks = K / TC_KC;

    tc_load_stage<GROUPED, PASSES>(sb + 0 * STAGE, rows_s, tid, 0, Ah, Al, B, m0, n0, K);
    CP_COMMIT();
    tc_load_stage<GROUPED, PASSES>(sb + 1 * STAGE, rows_s, tid, TC_KC, Ah, Al, B, m0, n0, K);
    CP_COMMIT();

    int stage = 0;
    for (int i = 0; i < nchunks; i++) {
        if (i + 1 < nchunks) { CP_WAIT(1); } else { CP_WAIT(0); }
        __syncthreads();

        if (i + 2 < nchunks) {
            int ps = stage + 2; if (ps >= TC_NSTAGE) ps -= TC_NSTAGE;
            tc_load_stage<GROUPED, PASSES>(sb + ps * STAGE, rows_s, tid,
                                           (i + 2) * TC_KC, Ah, Al, B, m0, n0, K);
            CP_COMMIT();
        }

        uint32_t st = sb + stage * STAGE;
        #pragma unroll
        for (int kk = 0; kk < 2; kk++) {
            const int vb = kk * 2 + (lane >> 4);
            uint32_t bf[8];
            #pragma unroll
            for (int p = 0; p < 2; p++) {
                int brow = wn * 32 + p * 16 + (lane & 15);
                uint32_t r[4];
                ldsm_x4(r, st + PASSES * A_TILE_B + swz_off(brow, vb));
                bf[4 * p + 0] = r[0]; bf[4 * p + 1] = r[2];
                bf[4 * p + 2] = r[1]; bf[4 * p + 3] = r[3];
            }
            uint32_t a[4][4];
            #pragma unroll
            for (int mt = 0; mt < 4; mt++) {
                int arow = wm * 64 + mt * 16 + (lane & 15);
                ldsm_x4(a[mt], st + swz_off(arow, vb));
            }
            #pragma unroll
            for (int mt = 0; mt < 4; mt++)
                #pragma unroll
                for (int nt = 0; nt < 4; nt++)
                    mma_f16(acc[mt][nt], a[mt], &bf[2 * nt]);
            if (PASSES == 2) {
                #pragma unroll
                for (int mt = 0; mt < 4; mt++) {
                    int arow = wm * 64 + mt * 16 + (lane & 15);
                    ldsm_x4(a[mt], st + A_TILE_B + swz_off(arow, vb));
                }
                #pragma unroll
                for (int mt = 0; mt < 4; mt++)
                    #pragma unroll
                    for (int nt = 0; nt < 4; nt++)
                        mma_f16(acc[mt][nt], a[mt], &bf[2 * nt]);
            }
        }
        stage = stage + 1; if (stage >= TC_NSTAGE) stage = 0;
    }

    // Epilogue
    const float* bias = (OUTMODE == 3) ? (n0 == 0 ? biasg : bias2)
                                       : biasg + (GROUPED ? (size_t)g * N : 0);
    float* outp = (OUTMODE == 3) ? (n0 == 0 ? OutF : OutF2) : OutF;
    #pragma unroll
    for (int mt = 0; mt < 4; mt++) {
        #pragma unroll
        for (int half = 0; half < 2; half++) {
            int rloc = wm * 64 + mt * 16 + (lane >> 2) + half * 8;
            int gm = GROUPED ? rows_s[rloc] : (m0 + rloc);
            if (GROUPED && gm < 0) continue;
            #pragma unroll
            for (int nt = 0; nt < 4; nt++) {
                int col = n0 + wn * 32 + nt * 8 + 2 * (lane & 3);
                int cl  = (OUTMODE == 3) ? (col - n0) : col;
                float c0 = acc[mt][nt][2 * half + 0] + bias[cl];
                float c1 = acc[mt][nt][2 * half + 1] + bias[cl + 1];
                if (RELU) { c0 = fmaxf(c0, 0.f); c1 = fmaxf(c1, 0.f); }
                if (OUTMODE == 0) {
                    *reinterpret_cast<float2*>(outp + (size_t)gm * N + col) =
                        make_float2(c0, c1);
                } else if (OUTMODE == 3) {
                    *reinterpret_cast<float2*>(outp + (size_t)gm * TC_BN + cl) =
                        make_float2(c0, c1);
                } else {
                    __half h0, h1, l0, l1;
                    split_f16(c0, h0, l0);
                    split_f16(c1, h1, l1);
                    __half2 ph = __halves2half2(h0, h1);
                    __half2 pl = __halves2half2(l0, l1);
                    *reinterpret_cast<uint32_t*>(Oh + (size_t)gm * N + col) =
                        *reinterpret_cast<uint32_t*>(&ph);
                    *reinterpret_cast<uint32_t*>(Ol + (size_t)gm * N + col) =
                        *reinterpret_cast<uint32_t*>(&pl);
                }
            }
        }
    }
}

// ---------------------------------------------------------------------------
// Reparameterize + fp16 hi/lo split
// ---------------------------------------------------------------------------
__global__ void z_k(const float* __restrict__ mu, const float* __restrict__ logvar,
                    const float* __restrict__ eps,
                    __half* __restrict__ Zh, __half* __restrict__ Zl, int n2) {
    int i = blockIdx.x * blockDim.x + threadIdx.x;
    if (i >= n2) return;
    float2 m  = reinterpret_cast<const float2*>(mu)[i];
    float2 lv = reinterpret_cast<const float2*>(logvar)[i];
    float2 e  = reinterpret_cast<const float2*>(eps)[i];
    float z0 = fmaf(e.x, expf(0.5f * lv.x), m.x);
    float z1 = fmaf(e.y, expf(0.5f * lv.y), m.y);
    __half h0, h1, l0, l1;
    split_f16(z0, h0, l0);
    split_f16(z1, h1, l1);
    __half2 ph = __halves2half2(h0, h1), pl = __halves2half2(l0, l1);
    reinterpret_cast<uint32_t*>(Zh)[i] = *reinterpret_cast<uint32_t*>(&ph);
    reinterpret_cast<uint32_t*>(Zl)[i] = *reinterpret_cast<uint32_t*>(&pl);
}

// ---------------------------------------------------------------------------
// Launcher
// ---------------------------------------------------------------------------
#define SMEM_P1 (TC_NSTAGE * (A_TILE_B + B_TILE_B) + TC_BM * 4)       // 74752
#define SMEM_P2 (TC_NSTAGE * (2 * A_TILE_B + B_TILE_B) + TC_BM * 4)   // 123904

extern "C" void kernel_launch(void* const* d_in, const int* in_sizes, int n_in,
                              void* d_out, int out_size) {
    const float* x        = (const float*)d_in[0];
    const int*   labels   = (const int*)  d_in[1];
    const float* eps      = (const float*)d_in[2];
    const float* W_enc0   = (const float*)d_in[3];
    const float* b_enc0   = (const float*)d_in[4];
    const float* W_enc1   = (const float*)d_in[5];
    const float* b_enc1   = (const float*)d_in[6];
    const float* W_mu     = (const float*)d_in[7];
    const float* b_mu     = (const float*)d_in[8];
    const float* W_logvar = (const float*)d_in[9];
    const float* b_logvar = (const float*)d_in[10];
    const float* W_dec0   = (const float*)d_in[11];
    const float* b_dec0   = (const float*)d_in[12];
    const float* W_dec1   = (const float*)d_in[13];
    const float* b_dec1   = (const float*)d_in[14];
    const float* W_out    = (const float*)d_in[15];
    const float* b_out    = (const float*)d_in[16];

    float* recon  = (float*)d_out;
    float* mu     = recon + (size_t)BSZ * DIN;
    float* logvar = mu    + (size_t)BSZ * LATD;

    __half *xh, *xl, *w0, *w1, *wmulv, *wd0, *wd1, *wo;
    __half *h0h, *h0l, *h1h, *h1l, *zh, *zl;
    cudaGetSymbolAddress((void**)&xh,  g_xh);   cudaGetSymbolAddress((void**)&xl,  g_xl);
    cudaGetSymbolAddress((void**)&w0,  g_w0);   cudaGetSymbolAddress((void**)&w1,  g_w1);
    cudaGetSymbolAddress((void**)&wmulv, g_wmulv);
    cudaGetSymbolAddress((void**)&wd0, g_wd0);  cudaGetSymbolAddress((void**)&wd1, g_wd1);
    cudaGetSymbolAddress((void**)&wo,  g_wo);
    cudaGetSymbolAddress((void**)&h0h, g_h0h);  cudaGetSymbolAddress((void**)&h0l, g_h0l);
    cudaGetSymbolAddress((void**)&h1h, g_h1h);  cudaGetSymbolAddress((void**)&h1l, g_h1l);
    cudaGetSymbolAddress((void**)&zh,  g_zh);   cudaGetSymbolAddress((void**)&zl,  g_zl);

    cudaFuncSetAttribute(tc_gemm_k<true,  true,  2, 1>,
                         cudaFuncAttributeMaxDynamicSharedMemorySize, SMEM_P1);
    cudaFuncSetAttribute(tc_gemm_k<false, false, 0, 1>,
                         cudaFuncAttributeMaxDynamicSharedMemorySize, SMEM_P1);
    cudaFuncSetAttribute(tc_gemm_k<true,  false, 2, 2>,
                         cudaFuncAttributeMaxDynamicSharedMemorySize, SMEM_P2);
    cudaFuncSetAttribute(tc_gemm_k<false, false, 3, 2>,
                         cudaFuncAttributeMaxDynamicSharedMemorySize, SMEM_P2);
    cudaFuncSetAttribute(tc_gemm_k<true,  true,  2, 2>,
                         cudaFuncAttributeMaxDynamicSharedMemorySize, SMEM_P2);

    // 1. routing
    reset_counts_k<<<1, 32>>>();
    scatter_k<<<BSZ / 256, 256>>>(labels);

    // 2. conversions (all weights -> single fp16 [N,K]; x -> fp16 hi/lo)
    convert_act_k<<<(BSZ * DIN / 4) / 256, 256>>>(x, xh, xl, BSZ * DIN / 4);
    convert_wt_k<<<dim3(H0D / 32, DIN / 32, NC), dim3(32, 8)>>>(W_enc0, w0, DIN, H0D);
    convert_wt_k<<<dim3(H1D / 32, H0D / 32, 1), dim3(32, 8)>>>(W_enc1, w1, H0D, H1D);
    convert_wt_k<<<dim3(LATD / 32, H1D / 32, 1), dim3(32, 8)>>>(W_mu, wmulv, H1D, LATD);
    convert_wt_k<<<dim3(LATD / 32, H1D / 32, 1), dim3(32, 8)>>>(W_logvar,
                                                wmulv + (size_t)LATD * H1D, H1D, LATD);
    convert_wt_k<<<dim3(H1D / 32, LATD / 32, 1), dim3(32, 8)>>>(W_dec0, wd0, LATD, H1D);
    convert_wt_k<<<dim3(H0D / 32, H1D / 32, NC), dim3(32, 8)>>>(W_dec1, wd1, H1D, H0D);
    convert_wt_k<<<dim3(DIN / 32, H0D / 32, 1), dim3(32, 8)>>>(W_out, wo, H0D, DIN);

    // 3. enc0 (grouped, 1-pass): h0 = relu(x @ W_enc0[c] + b) -> fp16 hi/lo
    tc_gemm_k<true, true, 2, 1><<<dim3(H0D / TC_BN, BSZ / TC_BM, NC), TC_THREADS, SMEM_P1>>>(
        xh, nullptr, w0, b_enc0, nullptr, nullptr, nullptr, h0h, h0l, BSZ, H0D, DIN);

    // 4. enc1 (2-pass): h1 = relu(h0 @ W_enc1 + b) -> fp16 hi/lo
    tc_gemm_k<true, false, 2, 2><<<dim3(H1D / TC_BN, BSZ / TC_BM, 1), TC_THREADS, SMEM_P2>>>(
        h0h, h0l, w1, b_enc1, nullptr, nullptr, nullptr, h1h, h1l, BSZ, H1D, H0D);

    // 5. mu+logvar fused (2-pass, N=256 split-output)
    tc_gemm_k<false, false, 3, 2><<<dim3(2, BSZ / TC_BM, 1), TC_THREADS, SMEM_P2>>>(
        h1h, h1l, wmulv, b_mu, b_logvar, mu, logvar, nullptr, nullptr,
        BSZ, 2 * LATD, H1D);

    // 6. reparameterize -> z fp16 hi/lo
    z_k<<<(BSZ * LATD / 2) / 256, 256>>>(mu, logvar, eps, zh, zl, BSZ * LATD / 2);

    // 7. dec0 (2-pass): d0 = relu(z @ W_dec0 + b) -> fp16 hi/lo (reuse h1 bufs)
    tc_gemm_k<true, false, 2, 2><<<dim3(H1D / TC_BN, BSZ / TC_BM, 1), TC_THREADS, SMEM_P2>>>(
        zh, zl, wd0, b_dec0, nullptr, nullptr, nullptr, h1h, h1l, BSZ, H1D, LATD);

    // 8. dec1 (grouped, 2-pass): d1 = relu(d0 @ W_dec1[c] + b) -> fp16 hi/lo (h0 bufs)
    tc_gemm_k<true, true, 2, 2><<<dim3(H0D / TC_BN, BSZ / TC_BM, NC), TC_THREADS, SMEM_P2>>>(
        h1h, h1l, wd1, b_dec1, nullptr, nullptr, nullptr, h0h, h0l, BSZ, H0D, H1D);

    // 9. out (1-pass): recon = d1 @ W_out + b -> fp32
    tc_gemm_k<false, false, 0, 1><<<dim3(DIN / TC_BN, BSZ / TC_BM, 1), TC_THREADS, SMEM_P1>>>(
        h0h, nullptr, wo, b_out, nullptr, recon, nullptr, nullptr, nullptr,
        BSZ, DIN, H0D);
}

// round 16
// speedup vs baseline: 2.2362x; 1.1530x over previous
#include <cuda_runtime.h>
#include <cuda_fp16.h>
#include <cstdint>
#include <math.h>

// ---------------------------------------------------------------------------
// Problem constants
// ---------------------------------------------------------------------------
#define BSZ   8192
#define DIN   2048
#define H0D   1024
#define H1D   512
#define LATD  128
#define NC    8

// ---------------------------------------------------------------------------
// Scratch (device globals) — all fp16
// ---------------------------------------------------------------------------
__device__ __half g_xh [(size_t)BSZ * DIN];       // x hi
__device__ __half g_w0 [(size_t)NC * H0D * DIN];  // enc0^T [C, H0, DIN]
__device__ __half g_w1 [(size_t)H1D * H0D];       // enc1^T
__device__ __half g_wmulv[(size_t)2 * LATD * H1D];// [mu^T ; logvar^T] 256 x H1
__device__ __half g_wd0[(size_t)H1D * LATD];      // dec0^T
__device__ __half g_wd1[(size_t)NC * H0D * H1D];  // dec1^T
__device__ __half g_wo [(size_t)DIN * H0D];       // out^T
__device__ __half g_h0h[(size_t)BSZ * H0D];       // h0 / d1 hi
__device__ __half g_h1h[(size_t)BSZ * H1D];       // h1 / d0 hi
__device__ __half g_h1l[(size_t)BSZ * H1D];       // h1 lo (mu needs exact A)
__device__ __half g_zh [(size_t)BSZ * LATD];
__device__ __half g_zl [(size_t)BSZ * LATD];
__device__ int    g_perm[NC * BSZ];
__device__ int    g_counts[NC];

// ---------------------------------------------------------------------------
// Routing
// ---------------------------------------------------------------------------
__global__ void reset_counts_k() {
    if (threadIdx.x < NC) g_counts[threadIdx.x] = 0;
}
__global__ void scatter_k(const int* __restrict__ labels) {
    int b = blockIdx.x * blockDim.x + threadIdx.x;
    if (b < BSZ) {
        int c = labels[b];
        int p = atomicAdd(&g_counts[c], 1);
        g_perm[c * BSZ + p] = b;
    }
}

// ---------------------------------------------------------------------------
// split helper
// ---------------------------------------------------------------------------
__device__ __forceinline__ void split_f16(float v, __half& h, __half& l) {
    h = __float2half_rn(v);
    l = __float2half_rn(v - __half2float(h));
}

// x -> fp16 hi only (enc0 is 1-pass)
__global__ void convert_act_k(const float* __restrict__ X,
                              __half* __restrict__ H, int n4) {
    int i = blockIdx.x * blockDim.x + threadIdx.x;
    if (i >= n4) return;
    float4 v = reinterpret_cast<const float4*>(X)[i];
    __half2 p0 = __floats2half2_rn(v.x, v.y);
    __half2 p1 = __floats2half2_rn(v.z, v.w);
    uint2 uh = make_uint2(*(uint32_t*)&p0, *(uint32_t*)&p1);
    *reinterpret_cast<uint2*>(H + (size_t)i * 4) = uh;
}

// Weight convert+transpose: W [K,N] fp32 -> T [N,K] fp16. grid.z = group.
__global__ void convert_wt_k(const float* __restrict__ W,
                             __half* __restrict__ T, int K, int N) {
    __shared__ float tile[32][33];
    int g = blockIdx.z;
    const float* Wg = W + (size_t)g * K * N;
    __half* Tg = T + (size_t)g * N * K;
    int n0 = blockIdx.x * 32, k0 = blockIdx.y * 32;
    int tx = threadIdx.x, ty = threadIdx.y;
    #pragma unroll
    for (int i = 0; i < 4; i++)
        tile[ty + 8 * i][tx] = Wg[(size_t)(k0 + ty + 8 * i) * N + n0 + tx];
    __syncthreads();
    #pragma unroll
    for (int i = 0; i < 4; i++) {
        float v = tile[tx][ty + 8 * i];
        Tg[(size_t)(n0 + ty + 8 * i) * K + k0 + tx] = __float2half_rn(v);
    }
}

// ---------------------------------------------------------------------------
// PTX wrappers
// ---------------------------------------------------------------------------
__device__ __forceinline__ uint32_t smem_u32(const void* p) {
    uint32_t a;
    asm("{ .reg .u64 t; cvta.to.shared.u64 t, %1; cvt.u32.u64 %0, t; }"
        : "=r"(a) : "l"(p));
    return a;
}

__device__ __forceinline__ void cp_async16(uint32_t saddr, const void* g, bool ok) {
    int sz = ok ? 16 : 0;
    asm volatile("cp.async.cg.shared.global [%0], [%1], 16, %2;"
                 :: "r"(saddr), "l"(g), "r"(sz));
}
#define CP_COMMIT() asm volatile("cp.async.commit_group;" ::: "memory")
#define CP_WAIT(n)  asm volatile("cp.async.wait_group %0;" :: "n"(n) : "memory")

__device__ __forceinline__ void ldsm_x4(uint32_t* r, uint32_t addr) {
    asm volatile("ldmatrix.sync.aligned.m8n8.x4.shared.b16 {%0,%1,%2,%3}, [%4];"
                 : "=r"(r[0]), "=r"(r[1]), "=r"(r[2]), "=r"(r[3]) : "r"(addr));
}

__device__ __forceinline__ void mma_f16(float* c, const uint32_t* a, const uint32_t* b) {
    asm volatile(
        "mma.sync.aligned.m16n8k16.row.col.f32.f16.f16.f32 "
        "{%0,%1,%2,%3}, {%4,%5,%6,%7}, {%8,%9}, {%0,%1,%2,%3};"
        : "+f"(c[0]), "+f"(c[1]), "+f"(c[2]), "+f"(c[3])
        : "r"(a[0]), "r"(a[1]), "r"(a[2]), "r"(a[3]), "r"(b[0]), "r"(b[1]));
}

// ---------------------------------------------------------------------------
// fp16 mma.sync GEMM: 256x128x32 CTA tile, 3-stage cp.async pipeline.
// PASSES=1: D = A_hi * B.   PASSES=2: D = A_hi * B + A_lo * B.
// OUTMODE: 0 = fp32, 2 = fp16 hi/lo, 3 = split fp32 (mu|logvar), 4 = fp16 hi
// ---------------------------------------------------------------------------
#define TC_BM 256
#define TC_BN 128
#define TC_KC 32
#define TC_THREADS 512
#define TC_NSTAGE 3
#define A_TILE_B (TC_BM * 64)          // 16384
#define B_TILE_B (TC_BN * 64)          // 8192

__device__ __forceinline__ uint32_t swz_off(int row, int v) {
    return (uint32_t)(row * 64 + ((v ^ ((row >> 1) & 3)) << 4));
}

template <bool GROUPED, int PASSES>
__device__ __forceinline__ void tc_load_stage(
    uint32_t stage_base, const int* __restrict__ rows, int tid, int k0,
    const __half* __restrict__ Ah, const __half* __restrict__ Al,
    const __half* __restrict__ B, int m0, int n0, int K)
{
    constexpr int A_OPS = PASSES * 1024;
    constexpr int NT = (A_OPS + 512) / TC_THREADS;  // 3 or 5
    #pragma unroll
    for (int t = 0; t < NT; t++) {
        int idx = tid + t * TC_THREADS;
        if (idx < A_OPS) {
            int tile = idx >> 10;
            int rem  = idx & 1023;
            int row  = rem >> 2;
            int v    = rem & 3;
            int gr = GROUPED ? rows[row] : (m0 + row);
            bool ok = !GROUPED || (gr >= 0);
            const __half* src = tile ? Al : Ah;
            cp_async16(stage_base + tile * A_TILE_B + swz_off(row, v),
                       src + ((size_t)(ok ? gr : 0) * K + k0 + v * 8), ok);
        } else {
            int j   = idx - A_OPS;     // 0..511
            int row = j >> 2;
            int v   = j & 3;
            cp_async16(stage_base + PASSES * A_TILE_B + swz_off(row, v),
                       B + ((size_t)(n0 + row) * K + k0 + v * 8), true);
        }
    }
}

template <bool RELU, bool GROUPED, int OUTMODE, int PASSES>
__global__ void __launch_bounds__(TC_THREADS, 1)
tc_gemm_k(const __half* __restrict__ Ah, const __half* __restrict__ Al,
          const __half* __restrict__ Bg,
          const float* __restrict__ biasg, const float* __restrict__ bias2,
          float* __restrict__ OutF, float* __restrict__ OutF2,
          __half* __restrict__ Oh, __half* __restrict__ Ol,
          int M, int N, int K)
{
    constexpr int STAGE = PASSES * A_TILE_B + B_TILE_B;
    constexpr int ROWS_OFF = TC_NSTAGE * STAGE;

    extern __shared__ char smem[];
    const int tid  = threadIdx.x;
    const int wid  = tid >> 5;
    const int lane = tid & 31;
    const int wm   = wid >> 2;
    const int wn   = wid & 3;
    const int g    = GROUPED ? blockIdx.z : 0;
    const int m0   = blockIdx.y * TC_BM;
    if (GROUPED) {
        if (m0 >= g_counts[g]) return;
    }
    const int n0 = blockIdx.x * TC_BN;
    uint32_t sb = smem_u32(smem);
    int* rows_s = reinterpret_cast<int*>(smem + ROWS_OFF);

    if (GROUPED) {
        if (tid < TC_BM) {
            int cnt = g_counts[g];
            int r = m0 + tid;
            rows_s[tid] = (r < cnt) ? g_perm[g * BSZ + r] : -1;
        }
        __syncthreads();
    }

    const __half* B = Bg + (GROUPED ? (size_t)g * N * K : 0);

    float acc[4][4][4];
    #pragma unroll
    for (int i = 0; i < 4; i++)
        #pragma unroll
        for (int j = 0; j < 4; j++)
            #pragma unroll
            for (int q = 0; q < 4; q++) acc[i][j][q] = 0.f;

    const int nchunks = K / TC_KC;

    tc_load_stage<GROUPED, PASSES>(sb + 0 * STAGE, rows_s, tid, 0, Ah, Al, B, m0, n0, K);
    CP_COMMIT();
    tc_load_stage<GROUPED, PASSES>(sb + 1 * STAGE, rows_s, tid, TC_KC, Ah, Al, B, m0, n0, K);
    CP_COMMIT();

    int stage = 0;
    for (int i = 0; i < nchunks; i++) {
        if (i + 1 < nchunks) { CP_WAIT(1); } else { CP_WAIT(0); }
        __syncthreads();

        if (i + 2 < nchunks) {
            int ps = stage + 2; if (ps >= TC_NSTAGE) ps -= TC_NSTAGE;
            tc_load_stage<GROUPED, PASSES>(sb + ps * STAGE, rows_s, tid,
                                           (i + 2) * TC_KC, Ah, Al, B, m0, n0, K);
            CP_COMMIT();
        }

        uint32_t st = sb + stage * STAGE;
        #pragma unroll
        for (int kk = 0; kk < 2; kk++) {
            const int vb = kk * 2 + (lane >> 4);
            uint32_t bf[8];
            #pragma unroll
            for (int p = 0; p < 2; p++) {
                int brow = wn * 32 + p * 16 + (lane & 15);
                uint32_t r[4];
                ldsm_x4(r, st + PASSES * A_TILE_B + swz_off(brow, vb));
                bf[4 * p + 0] = r[0]; bf[4 * p + 1] = r[2];
                bf[4 * p + 2] = r[1]; bf[4 * p + 3] = r[3];
            }
            uint32_t a[4][4];
            #pragma unroll
            for (int mt = 0; mt < 4; mt++) {
                int arow = wm * 64 + mt * 16 + (lane & 15);
                ldsm_x4(a[mt], st + swz_off(arow, vb));
            }
            #pragma unroll
            for (int mt = 0; mt < 4; mt++)
                #pragma unroll
                for (int nt = 0; nt < 4; nt++)
                    mma_f16(acc[mt][nt], a[mt], &bf[2 * nt]);
            if (PASSES == 2) {
                #pragma unroll
                for (int mt = 0; mt < 4; mt++) {
                    int arow = wm * 64 + mt * 16 + (lane & 15);
                    ldsm_x4(a[mt], st + A_TILE_B + swz_off(arow, vb));
                }
                #pragma unroll
                for (int mt = 0; mt < 4; mt++)
                    #pragma unroll
                    for (int nt = 0; nt < 4; nt++)
                        mma_f16(acc[mt][nt], a[mt], &bf[2 * nt]);
            }
        }
        stage = stage + 1; if (stage >= TC_NSTAGE) stage = 0;
    }

    // Epilogue
    const float* bias = (OUTMODE == 3) ? (n0 == 0 ? biasg : bias2)
                                       : biasg + (GROUPED ? (size_t)g * N : 0);
    float* outp = (OUTMODE == 3) ? (n0 == 0 ? OutF : OutF2) : OutF;
    #pragma unroll
    for (int mt = 0; mt < 4; mt++) {
        #pragma unroll
        for (int half = 0; half < 2; half++) {
            int rloc = wm * 64 + mt * 16 + (lane >> 2) + half * 8;
            int gm = GROUPED ? rows_s[rloc] : (m0 + rloc);
            if (GROUPED && gm < 0) continue;
            #pragma unroll
            for (int nt = 0; nt < 4; nt++) {
                int col = n0 + wn * 32 + nt * 8 + 2 * (lane & 3);
                int cl  = (OUTMODE == 3) ? (col - n0) : col;
                float c0 = acc[mt][nt][2 * half + 0] + bias[cl];
                float c1 = acc[mt][nt][2 * half + 1] + bias[cl + 1];
                if (RELU) { c0 = fmaxf(c0, 0.f); c1 = fmaxf(c1, 0.f); }
                if (OUTMODE == 0) {
                    *reinterpret_cast<float2*>(outp + (size_t)gm * N + col) =
                        make_float2(c0, c1);
                } else if (OUTMODE == 3) {
                    *reinterpret_cast<float2*>(outp + (size_t)gm * TC_BN + cl) =
                        make_float2(c0, c1);
                } else if (OUTMODE == 4) {
                    __half2 ph = __floats2half2_rn(c0, c1);
                    *reinterpret_cast<uint32_t*>(Oh + (size_t)gm * N + col) =
                        *reinterpret_cast<uint32_t*>(&ph);
                } else {
                    __half h0, h1, l0, l1;
                    split_f16(c0, h0, l0);
                    split_f16(c1, h1, l1);
                    __half2 ph = __halves2half2(h0, h1);
                    __half2 pl = __halves2half2(l0, l1);
                    *reinterpret_cast<uint32_t*>(Oh + (size_t)gm * N + col) =
                        *reinterpret_cast<uint32_t*>(&ph);
                    *reinterpret_cast<uint32_t*>(Ol + (size_t)gm * N + col) =
                        *reinterpret_cast<uint32_t*>(&pl);
                }
            }
        }
    }
}

// ---------------------------------------------------------------------------
// Reparameterize + fp16 hi/lo split
// ---------------------------------------------------------------------------
__global__ void z_k(const float* __restrict__ mu, const float* __restrict__ logvar,
                    const float* __restrict__ eps,
                    __half* __restrict__ Zh, __half* __restrict__ Zl, int n2) {
    int i = blockIdx.x * blockDim.x + threadIdx.x;
    if (i >= n2) return;
    float2 m  = reinterpret_cast<const float2*>(mu)[i];
    float2 lv = reinterpret_cast<const float2*>(logvar)[i];
    float2 e  = reinterpret_cast<const float2*>(eps)[i];
    float z0 = fmaf(e.x, expf(0.5f * lv.x), m.x);
    float z1 = fmaf(e.y, expf(0.5f * lv.y), m.y);
    __half h0, h1, l0, l1;
    split_f16(z0, h0, l0);
    split_f16(z1, h1, l1);
    __half2 ph = __halves2half2(h0, h1), pl = __halves2half2(l0, l1);
    reinterpret_cast<uint32_t*>(Zh)[i] = *reinterpret_cast<uint32_t*>(&ph);
    reinterpret_cast<uint32_t*>(Zl)[i] = *reinterpret_cast<uint32_t*>(&pl);
}

// ---------------------------------------------------------------------------
// Launcher
// ---------------------------------------------------------------------------
#define SMEM_P1 (TC_NSTAGE * (A_TILE_B + B_TILE_B) + TC_BM * 4)       // 74752
#define SMEM_P2 (TC_NSTAGE * (2 * A_TILE_B + B_TILE_B) + TC_BM * 4)   // 123904

extern "C" void kernel_launch(void* const* d_in, const int* in_sizes, int n_in,
                              void* d_out, int out_size) {
    const float* x        = (const float*)d_in[0];
    const int*   labels   = (const int*)  d_in[1];
    const float* eps      = (const float*)d_in[2];
    const float* W_enc0   = (const float*)d_in[3];
    const float* b_enc0   = (const float*)d_in[4];
    const float* W_enc1   = (const float*)d_in[5];
    const float* b_enc1   = (const float*)d_in[6];
    const float* W_mu     = (const float*)d_in[7];
    const float* b_mu     = (const float*)d_in[8];
    const float* W_logvar = (const float*)d_in[9];
    const float* b_logvar = (const float*)d_in[10];
    const float* W_dec0   = (const float*)d_in[11];
    const float* b_dec0   = (const float*)d_in[12];
    const float* W_dec1   = (const float*)d_in[13];
    const float* b_dec1   = (const float*)d_in[14];
    const float* W_out    = (const float*)d_in[15];
    const float* b_out    = (const float*)d_in[16];

    float* recon  = (float*)d_out;
    float* mu     = recon + (size_t)BSZ * DIN;
    float* logvar = mu    + (size_t)BSZ * LATD;

    __half *xh, *w0, *w1, *wmulv, *wd0, *wd1, *wo;
    __half *h0h, *h1h, *h1l, *zh, *zl;
    cudaGetSymbolAddress((void**)&xh,  g_xh);
    cudaGetSymbolAddress((void**)&w0,  g_w0);   cudaGetSymbolAddress((void**)&w1,  g_w1);
    cudaGetSymbolAddress((void**)&wmulv, g_wmulv);
    cudaGetSymbolAddress((void**)&wd0, g_wd0);  cudaGetSymbolAddress((void**)&wd1, g_wd1);
    cudaGetSymbolAddress((void**)&wo,  g_wo);
    cudaGetSymbolAddress((void**)&h0h, g_h0h);
    cudaGetSymbolAddress((void**)&h1h, g_h1h);  cudaGetSymbolAddress((void**)&h1l, g_h1l);
    cudaGetSymbolAddress((void**)&zh,  g_zh);   cudaGetSymbolAddress((void**)&zl,  g_zl);

    cudaFuncSetAttribute(tc_gemm_k<true,  true,  4, 1>,
                         cudaFuncAttributeMaxDynamicSharedMemorySize, SMEM_P1);
    cudaFuncSetAttribute(tc_gemm_k<true,  false, 2, 1>,
                         cudaFuncAttributeMaxDynamicSharedMemorySize, SMEM_P1);
    cudaFuncSetAttribute(tc_gemm_k<false, false, 3, 2>,
                         cudaFuncAttributeMaxDynamicSharedMemorySize, SMEM_P2);
    cudaFuncSetAttribute(tc_gemm_k<true,  false, 4, 2>,
                         cudaFuncAttributeMaxDynamicSharedMemorySize, SMEM_P2);
    cudaFuncSetAttribute(tc_gemm_k<true,  true,  4, 1>,
                         cudaFuncAttributeMaxDynamicSharedMemorySize, SMEM_P1);
    cudaFuncSetAttribute(tc_gemm_k<false, false, 0, 1>,
                         cudaFuncAttributeMaxDynamicSharedMemorySize, SMEM_P1);

    // 1. routing
    reset_counts_k<<<1, 32>>>();
    scatter_k<<<BSZ / 256, 256>>>(labels);

    // 2. conversions (weights -> fp16 [N,K]; x -> fp16 hi)
    convert_act_k<<<(BSZ * DIN / 4) / 256, 256>>>(x, xh, BSZ * DIN / 4);
    convert_wt_k<<<dim3(H0D / 32, DIN / 32, NC), dim3(32, 8)>>>(W_enc0, w0, DIN, H0D);
    convert_wt_k<<<dim3(H1D / 32, H0D / 32, 1), dim3(32, 8)>>>(W_enc1, w1, H0D, H1D);
    convert_wt_k<<<dim3(LATD / 32, H1D / 32, 1), dim3(32, 8)>>>(W_mu, wmulv, H1D, LATD);
    convert_wt_k<<<dim3(LATD / 32, H1D / 32, 1), dim3(32, 8)>>>(W_logvar,
                                                wmulv + (size_t)LATD * H1D, H1D, LATD);
    convert_wt_k<<<dim3(H1D / 32, LATD / 32, 1), dim3(32, 8)>>>(W_dec0, wd0, LATD, H1D);
    convert_wt_k<<<dim3(H0D / 32, H1D / 32, NC), dim3(32, 8)>>>(W_dec1, wd1, H1D, H0D);
    convert_wt_k<<<dim3(DIN / 32, H0D / 32, 1), dim3(32, 8)>>>(W_out, wo, H0D, DIN);

    // 3. enc0 (grouped, 1-pass): h0 = relu(x @ W_enc0[c] + b) -> fp16 hi
    tc_gemm_k<true, true, 4, 1><<<dim3(H0D / TC_BN, BSZ / TC_BM, NC), TC_THREADS, SMEM_P1>>>(
        xh, nullptr, w0, b_enc0, nullptr, nullptr, nullptr, h0h, nullptr, BSZ, H0D, DIN);

    // 4. enc1 (1-pass): h1 = relu(h0 @ W_enc1 + b) -> fp16 hi/lo (mu needs exact A)
    tc_gemm_k<true, false, 2, 1><<<dim3(H1D / TC_BN, BSZ / TC_BM, 1), TC_THREADS, SMEM_P1>>>(
        h0h, nullptr, w1, b_enc1, nullptr, nullptr, nullptr, h1h, h1l, BSZ, H1D, H0D);

    // 5. mu+logvar fused (2-pass, N=256 split-output)
    tc_gemm_k<false, false, 3, 2><<<dim3(2, BSZ / TC_BM, 1), TC_THREADS, SMEM_P2>>>(
        h1h, h1l, wmulv, b_mu, b_logvar, mu, logvar, nullptr, nullptr,
        BSZ, 2 * LATD, H1D);

    // 6. reparameterize -> z fp16 hi/lo
    z_k<<<(BSZ * LATD / 2) / 256, 256>>>(mu, logvar, eps, zh, zl, BSZ * LATD / 2);

    // 7. dec0 (2-pass): d0 = relu(z @ W_dec0 + b) -> fp16 hi (reuse h1 buf)
    tc_gemm_k<true, false, 4, 2><<<dim3(H1D / TC_BN, BSZ / TC_BM, 1), TC_THREADS, SMEM_P2>>>(
        zh, zl, wd0, b_dec0, nullptr, nullptr, nullptr, h1h, nullptr, BSZ, H1D, LATD);

    // 8. dec1 (grouped, 1-pass): d1 = relu(d0 @ W_dec1[c] + b) -> fp16 hi (h0 buf)
    tc_gemm_k<true, true, 4, 1><<<dim3(H0D / TC_BN, BSZ / TC_BM, NC), TC_THREADS, SMEM_P1>>>(
        h1h, nullptr, wd1, b_dec1, nullptr, nullptr, nullptr, h0h, nullptr, BSZ, H0D, H1D);

    // 9. out (1-pass): recon = d1 @ W_out + b -> fp32
    tc_gemm_k<false, false, 0, 1><<<dim3(DIN / TC_BN, BSZ / TC_BM, 1), TC_THREADS, SMEM_P1>>>(
        h0h, nullptr, wo, b_out, nullptr, recon, nullptr, nullptr, nullptr,
        BSZ, DIN, H0D);
}